// round 2
// baseline (speedup 1.0000x reference)
#include <cuda_runtime.h>
#include <math.h>

#define NS 48
#define NV 10
#define NE 100000
#define NN 10000
#define NF 144
#define IND 78
#define WNUM 3364
#define EPB 128
#define NBLK ((NE + EPB - 1) / EPB)
#define A_SS 0.102062072615966f   /* 1/sqrt(96) = a_ss = a_sv */
#define A_VV 0.223606797749979f   /* 1/sqrt(20) = a_vs = a_vv */
#define ISQ3 0.577350269189626f
#define EPSF 1e-5f

/* device scratch (no runtime allocation) */
__device__ float g_h[(size_t)NE * NF];
__device__ float g_sum[NN * IND];
__device__ float g_cnt[NN];
__device__ float g_pre[NN * IND];
__device__ float g_stat[2 * NS + NV];   /* sumS[48], sumSS[48], sumV2[10] */
__device__ float g_nrm[2 * NS + NV];    /* scaleS[48], shiftS[48], scaleV[10] */

__global__ void k_zero() {
    int i = blockIdx.x * blockDim.x + threadIdx.x, st = gridDim.x * blockDim.x;
    for (int x = i; x < NN * IND; x += st) g_sum[x] = 0.f;
    for (int x = i; x < NN; x += st) g_cnt[x] = 0.f;
    if (i < 2 * NS + NV) g_stat[i] = 0.f;
}

/* ---------------- fc1 + relu -> g_h ---------------- */
/* 128 edges/block, 256 threads (tx 0..7 -> 18 cols, ty 0..31 -> 4 edges) */
__global__ __launch_bounds__(256, 1) void k_fc1(const float* __restrict__ ea,
                                                const float* __restrict__ w1,
                                                const float* __restrict__ b1) {
    extern __shared__ float sm[];
    float* sE = sm;            /* [144][132] transposed edge_attr tile */
    float* sW = sm + 19008;    /* [144][144] */
    int tid = threadIdx.x, tx = tid & 7, ty = tid >> 3;
    int e0 = blockIdx.x * EPB;

    for (int x = tid; x < EPB * NF; x += 256) {
        int e = x / NF, k = x - e * NF;
        sE[k * 132 + e] = (e0 + e < NE) ? ea[(size_t)(e0 + e) * NF + k] : 0.f;
    }
    for (int x = tid; x < NF * NF; x += 256) sW[x] = w1[x];
    __syncthreads();

    float acc[4][18];
#pragma unroll
    for (int r = 0; r < 4; r++)
#pragma unroll
        for (int j = 0; j < 18; j++) acc[r][j] = 0.f;

    for (int k = 0; k < NF; k++) {
        float4 hv = *(const float4*)&sE[k * 132 + ty * 4];
        float wv[18];
#pragma unroll
        for (int j = 0; j < 18; j++) wv[j] = sW[k * NF + tx * 18 + j];
#pragma unroll
        for (int j = 0; j < 18; j++) {
            acc[0][j] = fmaf(hv.x, wv[j], acc[0][j]);
            acc[1][j] = fmaf(hv.y, wv[j], acc[1][j]);
            acc[2][j] = fmaf(hv.z, wv[j], acc[2][j]);
            acc[3][j] = fmaf(hv.w, wv[j], acc[3][j]);
        }
    }
#pragma unroll
    for (int r = 0; r < 4; r++) {
        int e = e0 + ty * 4 + r;
        if (e < NE) {
#pragma unroll
            for (int j = 0; j < 18; j++) {
                int o = tx * 18 + j;
                g_h[(size_t)e * NF + o] = fmaxf(acc[r][j] + b1[o], 0.f);
            }
        }
    }
}

/* -------- fused fc2 + tensor product + scatter -------- */
/* 128 edges/block, 256 threads (tx 0..7 cols x4, ty 0..31 edges x4) */
__global__ __launch_bounds__(256, 1) void k_main(const float* __restrict__ na,
                                                 const float* __restrict__ esh,
                                                 const float* __restrict__ w2,
                                                 const float* __restrict__ b2,
                                                 const int* __restrict__ ei) {
    extern __shared__ float sm[];
    float* sH = sm;              /* [144][132] h tile (transposed)      */
    float* sW = sm + 19008;      /* [144][32] fc2 col tile              */
    float* sB = sm + 23616;      /* [32] fc2 bias tile                  */
    float* sU = sm + 23648;      /* [128][48] a_sv*xs                   */
    float* sV = sm + 29792;      /* [128][30] a_vv*xv                   */
    float* sC = sm + 33632;      /* [128][10] a_vs*dot                  */
    float* s0 = sm + 34912;      /* [128]                               */
    float* s1 = sm + 35040;      /* [128][3]                            */
    int*   sS = (int*)(sm + 35424); /* [128] src node                   */
    float* aS = sm + 35552;      /* [128][48] out_s accumulator         */
    float* aP = sm + 41696;      /* [128][10] p accumulator             */
    float* aQ = sm + 42976;      /* [128][30] q accumulator             */
    int tid = threadIdx.x, tx = tid & 7, ty = tid >> 3;
    int e0 = blockIdx.x * EPB;

    for (int x = tid; x < EPB * NF; x += 256) {
        int e = x / NF, k = x - e * NF;
        sH[k * 132 + e] = (e0 + e < NE) ? g_h[(size_t)(e0 + e) * NF + k] : 0.f;
    }
    for (int x = tid; x < EPB * IND; x += 256) {
        int e = x / IND, d = x - e * IND;
        float v = 0.f;
        if (e0 + e < NE) { int dst = ei[NE + e0 + e]; v = na[dst * IND + d]; }
        if (d < NS) sU[e * NS + d] = A_SS * v;
        else        sV[e * 30 + d - NS] = A_VV * v;
    }
    if (tid < EPB) {
        int eg = e0 + tid;
        if (eg < NE) {
            sS[tid] = ei[eg]; s0[tid] = esh[eg * 4];
            s1[tid * 3] = esh[eg * 4 + 1]; s1[tid * 3 + 1] = esh[eg * 4 + 2];
            s1[tid * 3 + 2] = esh[eg * 4 + 3];
        } else {
            sS[tid] = 0; s0[tid] = 0.f;
            s1[tid * 3] = s1[tid * 3 + 1] = s1[tid * 3 + 2] = 0.f;
        }
    }
    for (int x = tid; x < EPB * 88; x += 256) aS[x] = 0.f; /* aS,aP,aQ contiguous */
    __syncthreads();
    for (int x = tid; x < EPB * NV; x += 256) {
        int e = x / NV, i = x - e * NV;
        sC[x] = ISQ3 * (sV[e * 30 + i * 3] * s1[e * 3] +
                        sV[e * 30 + i * 3 + 1] * s1[e * 3 + 1] +
                        sV[e * 30 + i * 3 + 2] * s1[e * 3 + 2]);
    }
    __syncthreads();

    int c0 = 0;
    for (int t = 0; t < 106; t++, c0 += 32) {
        for (int x = tid; x < NF * 32; x += 256) {
            int k = x >> 5, c = x & 31, gc = c0 + c;
            sW[x] = (gc < WNUM) ? w2[(size_t)k * WNUM + gc] : 0.f;
        }
        if (tid < 32) sB[tid] = (c0 + tid < WNUM) ? b2[c0 + tid] : 0.f;
        __syncthreads();

        float wr[4][4] = {{0.f,0.f,0.f,0.f},{0.f,0.f,0.f,0.f},
                          {0.f,0.f,0.f,0.f},{0.f,0.f,0.f,0.f}};
#pragma unroll 4
        for (int k = 0; k < NF; k++) {
            float4 wv = *(const float4*)&sW[k * 32 + tx * 4];
            float4 hv = *(const float4*)&sH[k * 132 + ty * 4];
            wr[0][0] = fmaf(hv.x, wv.x, wr[0][0]); wr[0][1] = fmaf(hv.x, wv.y, wr[0][1]);
            wr[0][2] = fmaf(hv.x, wv.z, wr[0][2]); wr[0][3] = fmaf(hv.x, wv.w, wr[0][3]);
            wr[1][0] = fmaf(hv.y, wv.x, wr[1][0]); wr[1][1] = fmaf(hv.y, wv.y, wr[1][1]);
            wr[1][2] = fmaf(hv.y, wv.z, wr[1][2]); wr[1][3] = fmaf(hv.y, wv.w, wr[1][3]);
            wr[2][0] = fmaf(hv.z, wv.x, wr[2][0]); wr[2][1] = fmaf(hv.z, wv.y, wr[2][1]);
            wr[2][2] = fmaf(hv.z, wv.z, wr[2][2]); wr[2][3] = fmaf(hv.z, wv.w, wr[2][3]);
            wr[3][0] = fmaf(hv.w, wv.x, wr[3][0]); wr[3][1] = fmaf(hv.w, wv.y, wr[3][1]);
            wr[3][2] = fmaf(hv.w, wv.z, wr[3][2]); wr[3][3] = fmaf(hv.w, wv.w, wr[3][3]);
        }
        __syncthreads();

#pragma unroll
        for (int j = 0; j < 4; j++) {
            int c = c0 + tx * 4 + j;
            if (c < WNUM) {
                float bb = sB[tx * 4 + j];
                if (c < 2304) {
                    int i = c / 48, o = c - i * 48;
#pragma unroll
                    for (int r = 0; r < 4; r++) {
                        int e = ty * 4 + r;
                        atomicAdd(&aS[e * 48 + o], s0[e] * sU[e * 48 + i] * (wr[r][j] + bb));
                    }
                } else if (c < 2784) {
                    int tt = c - 2304, i = tt / 48, o = tt - i * 48;
#pragma unroll
                    for (int r = 0; r < 4; r++) {
                        int e = ty * 4 + r;
                        atomicAdd(&aS[e * 48 + o], sC[e * 10 + i] * (wr[r][j] + bb));
                    }
                } else if (c < 3264) {
                    int tt = c - 2784, i = tt / 10, o = tt - i * 10;
#pragma unroll
                    for (int r = 0; r < 4; r++) {
                        int e = ty * 4 + r;
                        atomicAdd(&aP[e * 10 + o], sU[e * 48 + i] * (wr[r][j] + bb));
                    }
                } else {
                    int tt = c - 3264, i = tt / 10, o = tt - i * 10;
#pragma unroll
                    for (int r = 0; r < 4; r++) {
                        int e = ty * 4 + r;
                        float w = wr[r][j] + bb;
                        atomicAdd(&aQ[e * 30 + o * 3],     sV[e * 30 + i * 3] * w);
                        atomicAdd(&aQ[e * 30 + o * 3 + 1], sV[e * 30 + i * 3 + 1] * w);
                        atomicAdd(&aQ[e * 30 + o * 3 + 2], sV[e * 30 + i * 3 + 2] * w);
                    }
                }
            }
        }
        __syncthreads();
    }

    /* scatter tp into node sums */
    for (int x = tid; x < EPB * IND; x += 256) {
        int e = x / IND, d = x - e * IND;
        if (e0 + e < NE) {
            float v;
            if (d < NS) v = aS[e * 48 + d];
            else {
                int tt = d - NS, o = tt / 3, cc = tt - o * 3;
                v = s1[e * 3 + cc] * aP[e * 10 + o] + s0[e] * aQ[e * 30 + tt];
            }
            atomicAdd(&g_sum[sS[e] * IND + d], v);
        }
    }
    if (tid < EPB && e0 + tid < NE) atomicAdd(&g_cnt[sS[tid]], 1.f);
}

/* ---------------- epilogue ---------------- */
__global__ void k_pre(const float* __restrict__ na) {
    int i = blockIdx.x * blockDim.x + threadIdx.x, st = gridDim.x * blockDim.x;
    for (int x = i; x < NN * IND; x += st) {
        int n = x / IND;
        g_pre[x] = g_sum[x] / fmaxf(g_cnt[n], 1.f) + na[x];
    }
}

__global__ __launch_bounds__(256) void k_stat() {
    __shared__ float r1[256], r2[256];
    int b = blockIdx.x, tid = threadIdx.x;
    float s = 0.f, q = 0.f;
    if (b < NS) {
        for (int n = tid; n < NN; n += 256) { float v = g_pre[n * IND + b]; s += v; q += v * v; }
    } else {
        int i = b - NS;
        for (int n = tid; n < NN; n += 256) {
            const float* p = &g_pre[n * IND + NS + i * 3];
            s += p[0] * p[0] + p[1] * p[1] + p[2] * p[2];
        }
    }
    r1[tid] = s; r2[tid] = q; __syncthreads();
    for (int o = 128; o > 0; o >>= 1) {
        if (tid < o) { r1[tid] += r1[tid + o]; r2[tid] += r2[tid + o]; }
        __syncthreads();
    }
    if (tid == 0) {
        if (b < NS) { g_stat[b] = r1[0]; g_stat[NS + b] = r2[0]; }
        else g_stat[NS + b] = r1[0];   /* b in [48,58) -> idx 96..105 */
    }
}

__global__ void k_nrm(const float* __restrict__ bnw, const float* __restrict__ bnb) {
    int t = threadIdx.x;
    if (t < NS) {
        float mu = g_stat[t] * (1.f / NN);
        float var = g_stat[NS + t] * (1.f / NN) - mu * mu;
        float sc = bnw[t] * rsqrtf(var + EPSF);
        g_nrm[t] = sc; g_nrm[NS + t] = bnb[t] - mu * sc;
    } else if (t < NS + NV) {
        int i = t - NS;
        float fn = g_stat[2 * NS + i] * (1.f / (3.f * NN));
        g_nrm[2 * NS + i] = bnw[NS + i] * rsqrtf(fn + EPSF);
    }
}

__global__ void k_apply(float* __restrict__ out) {
    int i = blockIdx.x * blockDim.x + threadIdx.x, st = gridDim.x * blockDim.x;
    for (int x = i; x < NN * IND; x += st) {
        int n = x / IND, d = x - n * IND;
        out[x] = (d < NS) ? g_pre[x] * g_nrm[d] + g_nrm[NS + d]
                          : g_pre[x] * g_nrm[2 * NS + (d - NS) / 3];
    }
}

extern "C" void kernel_launch(void* const* d_in, const int* in_sizes, int n_in,
                              void* d_out, int out_size) {
    (void)in_sizes; (void)n_in; (void)out_size;
    const float* nattr = (const float*)d_in[0];
    const float* ea    = (const float*)d_in[1];
    const float* esh   = (const float*)d_in[2];
    const float* w1    = (const float*)d_in[3];
    const float* b1    = (const float*)d_in[4];
    const float* w2    = (const float*)d_in[5];
    const float* b2    = (const float*)d_in[6];
    const float* bnw   = (const float*)d_in[7];
    const float* bnb   = (const float*)d_in[8];
    const int*   ei    = (const int*)d_in[9];
    float* out = (float*)d_out;

    size_t sm1 = (size_t)(19008 + 20736) * 4;   /* 158,976 B */
    size_t sm2 = (size_t)46816 * 4;             /* 187,264 B */
    cudaFuncSetAttribute(k_fc1,  cudaFuncAttributeMaxDynamicSharedMemorySize, (int)sm1);
    cudaFuncSetAttribute(k_main, cudaFuncAttributeMaxDynamicSharedMemorySize, (int)sm2);

    k_zero<<<512, 256>>>();
    k_fc1<<<NBLK, 256, sm1>>>(ea, w1, b1);
    k_main<<<NBLK, 256, sm2>>>(nattr, esh, w2, b2, ei);
    k_pre<<<512, 256>>>(nattr);
    k_stat<<<NS + NV, 256>>>();
    k_nrm<<<1, 64>>>(bnw, bnb);
    k_apply<<<512, 256>>>(out);
}

// round 3
// speedup vs baseline: 1.4266x; 1.4266x over previous
#include <cuda_runtime.h>
#include <math.h>

#define NS 48
#define NV 10
#define NE 100000
#define NN 10000
#define NF 144
#define IND 78
#define WNUM 3364
#define EPB 128
#define NBLK ((NE + EPB - 1) / EPB)
#define NCHUNK 71            /* 70 full 48-col chunks + 1 partial (4 cols) */
#define A_SS 0.102062072615966f   /* 1/sqrt(96) = a_ss = a_sv */
#define A_VV 0.223606797749979f   /* 1/sqrt(20) = a_vs = a_vv */
#define ISQ3 0.577350269189626f
#define EPSF 1e-5f

/* device scratch (no runtime allocation) */
__device__ float g_h[(size_t)NE * NF];
__device__ float g_sum[NN * IND];
__device__ float g_cnt[NN];
__device__ float g_pre[NN * IND];
__device__ float g_stat[2 * NS + NV];
__device__ float g_nrm[2 * NS + NV];

__global__ void k_zero() {
    int i = blockIdx.x * blockDim.x + threadIdx.x, st = gridDim.x * blockDim.x;
    for (int x = i; x < NN * IND; x += st) g_sum[x] = 0.f;
    for (int x = i; x < NN; x += st) g_cnt[x] = 0.f;
    if (i < 2 * NS + NV) g_stat[i] = 0.f;
}

/* ---------------- fc1 + relu -> g_h ---------------- */
__global__ __launch_bounds__(256, 1) void k_fc1(const float* __restrict__ ea,
                                                const float* __restrict__ w1,
                                                const float* __restrict__ b1) {
    extern __shared__ float sm[];
    float* sE = sm;            /* [144][132] transposed edge_attr tile */
    float* sW = sm + 19008;    /* [144][144] */
    int tid = threadIdx.x, tx = tid & 7, ty = tid >> 3;
    int e0 = blockIdx.x * EPB;

    for (int x = tid; x < EPB * NF; x += 256) {
        int e = x / NF, k = x - e * NF;
        sE[k * 132 + e] = (e0 + e < NE) ? ea[(size_t)(e0 + e) * NF + k] : 0.f;
    }
    for (int x = tid; x < NF * NF; x += 256) sW[x] = w1[x];
    __syncthreads();

    float acc[4][18];
#pragma unroll
    for (int r = 0; r < 4; r++)
#pragma unroll
        for (int j = 0; j < 18; j++) acc[r][j] = 0.f;

    for (int k = 0; k < NF; k++) {
        float4 hv = *(const float4*)&sE[k * 132 + ty * 4];
        float wv[18];
#pragma unroll
        for (int j = 0; j < 18; j++) wv[j] = sW[k * NF + tx * 18 + j];
#pragma unroll
        for (int j = 0; j < 18; j++) {
            acc[0][j] = fmaf(hv.x, wv[j], acc[0][j]);
            acc[1][j] = fmaf(hv.y, wv[j], acc[1][j]);
            acc[2][j] = fmaf(hv.z, wv[j], acc[2][j]);
            acc[3][j] = fmaf(hv.w, wv[j], acc[3][j]);
        }
    }
#pragma unroll
    for (int r = 0; r < 4; r++) {
        int e = e0 + ty * 4 + r;
        if (e < NE) {
#pragma unroll
            for (int j = 0; j < 18; j++) {
                int o = tx * 18 + j;
                g_h[(size_t)e * NF + o] = fmaxf(acc[r][j] + b1[o], 0.f);
            }
        }
    }
}

/* -------- fused fc2 + tensor product + scatter (48-col aligned chunks) --- */
/* 256 threads: tx 0..7 -> 6 cols each, ty 0..31 -> 4 edges each            */
__global__ __launch_bounds__(256, 1) void k_main(const float* __restrict__ na,
                                                 const float* __restrict__ esh,
                                                 const float* __restrict__ w2,
                                                 const float* __restrict__ b2,
                                                 const int* __restrict__ ei) {
    extern __shared__ float sm[];
    float* sH  = sm;             /* [144][132] h tile (transposed)  19008 */
    float* sW  = sm + 19008;     /* [144][48] fc2 col chunk          6912 */
    float* sB  = sm + 25920;     /* [48] bias chunk                    48 */
    float* sCS = sm + 25968;     /* [128][58] combined out_s coeffs  7424 */
    float* sU  = sm + 33392;     /* [128][48] a_sv*xs                6144 */
    float* sV  = sm + 39536;     /* [128][30] a_vv*xv                3840 */
    float* s0  = sm + 43376;     /* [128]                             128 */
    float* s1  = sm + 43504;     /* [128][3]                          384 */
    int*   sS  = (int*)(sm + 43888); /* [128] src node                128 */
    float* aP  = sm + 44016;     /* [128][10]                        1280 */
    float* aQ  = sm + 45296;     /* [128][30]                        3840 */
    int tid = threadIdx.x, tx = tid & 7, ty = tid >> 3;
    int e0 = blockIdx.x * EPB;

    for (int x = tid; x < EPB * NF; x += 256) {
        int e = x / NF, k = x - e * NF;
        sH[k * 132 + e] = (e0 + e < NE) ? g_h[(size_t)(e0 + e) * NF + k] : 0.f;
    }
    for (int x = tid; x < EPB * IND; x += 256) {
        int e = x / IND, d = x - e * IND;
        float v = 0.f;
        if (e0 + e < NE) { int dst = ei[NE + e0 + e]; v = na[dst * IND + d]; }
        if (d < NS) sU[e * NS + d] = A_SS * v;
        else        sV[e * 30 + d - NS] = A_VV * v;
    }
    if (tid < EPB) {
        int eg = e0 + tid;
        if (eg < NE) {
            sS[tid] = ei[eg]; s0[tid] = esh[eg * 4];
            s1[tid * 3] = esh[eg * 4 + 1]; s1[tid * 3 + 1] = esh[eg * 4 + 2];
            s1[tid * 3 + 2] = esh[eg * 4 + 3];
        } else {
            sS[tid] = 0; s0[tid] = 0.f;
            s1[tid * 3] = s1[tid * 3 + 1] = s1[tid * 3 + 2] = 0.f;
        }
    }
    for (int x = tid; x < EPB * 40; x += 256) aP[x] = 0.f;  /* aP,aQ contiguous */
    __syncthreads();
    /* combined coefficients for out_s: i<48 -> s0*a_ss*xs ; i in 48..57 -> a_vs*dot/sqrt3 */
    for (int x = tid; x < EPB * 58; x += 256) {
        int e = x / 58, i = x - e * 58;
        if (i < 48) sCS[x] = s0[e] * sU[e * 48 + i];
        else {
            int ii = i - 48;
            sCS[x] = ISQ3 * (sV[e * 30 + ii * 3] * s1[e * 3] +
                             sV[e * 30 + ii * 3 + 1] * s1[e * 3 + 1] +
                             sV[e * 30 + ii * 3 + 2] * s1[e * 3 + 2]);
        }
    }
    __syncthreads();

    float acc[4][6];
#pragma unroll
    for (int r = 0; r < 4; r++)
#pragma unroll
        for (int j = 0; j < 6; j++) acc[r][j] = 0.f;

    for (int ch = 0; ch < NCHUNK; ch++) {
        int c0 = ch * 48;
        /* load weight chunk [144][48] (zero-pad past WNUM), float4 vectorized */
        for (int x = tid; x < NF * 12; x += 256) {
            int k = x / 12, q = x - k * 12;
            int gc = c0 + q * 4;
            float4 v = make_float4(0.f, 0.f, 0.f, 0.f);
            if (gc + 3 < WNUM) v = *(const float4*)&w2[(size_t)k * WNUM + gc];
            *(float4*)&sW[k * 48 + q * 4] = v;
        }
        if (tid < 48) sB[tid] = (c0 + tid < WNUM) ? b2[c0 + tid] : 0.f;
        __syncthreads();

        float wr[4][6];
#pragma unroll
        for (int r = 0; r < 4; r++)
#pragma unroll
            for (int j = 0; j < 6; j++) wr[r][j] = 0.f;

#pragma unroll 4
        for (int k = 0; k < NF; k++) {
            float4 hv = *(const float4*)&sH[k * 132 + ty * 4];
            float h4[4] = {hv.x, hv.y, hv.z, hv.w};
            float2 wa = *(const float2*)&sW[k * 48 + tx * 6];
            float2 wb = *(const float2*)&sW[k * 48 + tx * 6 + 2];
            float2 wc = *(const float2*)&sW[k * 48 + tx * 6 + 4];
            float w6[6] = {wa.x, wa.y, wb.x, wb.y, wc.x, wc.y};
#pragma unroll
            for (int r = 0; r < 4; r++)
#pragma unroll
                for (int j = 0; j < 6; j++)
                    wr[r][j] = fmaf(h4[r], w6[j], wr[r][j]);
        }

        float bb[6];
#pragma unroll
        for (int j = 0; j < 6; j++) bb[j] = sB[tx * 6 + j];

        if (ch < 58) {
            /* ss (ch<48, i=ch) and vs (i=ch-48+48): pure register accumulate */
#pragma unroll
            for (int r = 0; r < 4; r++) {
                float cf = sCS[(ty * 4 + r) * 58 + ch];
#pragma unroll
                for (int j = 0; j < 6; j++)
                    acc[r][j] = fmaf(cf, wr[r][j] + bb[j], acc[r][j]);
            }
        } else if (ch < 68) {
            /* sv: p[e,o] += u[e,i]*(w+b) */
#pragma unroll
            for (int j = 0; j < 6; j++) {
                int tt = (ch - 58) * 48 + tx * 6 + j;
                int i = tt / 10, o = tt - i * 10;
#pragma unroll
                for (int r = 0; r < 4; r++) {
                    int e = ty * 4 + r;
                    atomicAdd(&aP[e * 10 + o], sU[e * 48 + i] * (wr[r][j] + bb[j]));
                }
            }
        } else {
            /* vv: q[e,o,c] += v[e,i,c]*(w+b) */
#pragma unroll
            for (int j = 0; j < 6; j++) {
                int tt = (ch - 68) * 48 + tx * 6 + j;
                if (tt < 100) {
                    int i = tt / 10, o = tt - i * 10;
#pragma unroll
                    for (int r = 0; r < 4; r++) {
                        int e = ty * 4 + r;
                        float w = wr[r][j] + bb[j];
                        atomicAdd(&aQ[e * 30 + o * 3],     sV[e * 30 + i * 3] * w);
                        atomicAdd(&aQ[e * 30 + o * 3 + 1], sV[e * 30 + i * 3 + 1] * w);
                        atomicAdd(&aQ[e * 30 + o * 3 + 2], sV[e * 30 + i * 3 + 2] * w);
                    }
                }
            }
        }
        __syncthreads();
    }

    /* scatter out_s straight from registers */
#pragma unroll
    for (int r = 0; r < 4; r++) {
        int e = ty * 4 + r;
        if (e0 + e < NE) {
            int base = sS[e] * IND + tx * 6;
#pragma unroll
            for (int j = 0; j < 6; j++) atomicAdd(&g_sum[base + j], acc[r][j]);
        }
    }
    /* vector part: assemble from aP/aQ and scatter */
    for (int x = tid; x < EPB * 30; x += 256) {
        int e = x / 30, t = x - e * 30, o = t / 3, cc = t - o * 3;
        if (e0 + e < NE) {
            float v = s1[e * 3 + cc] * aP[e * 10 + o] + s0[e] * aQ[e * 30 + t];
            atomicAdd(&g_sum[sS[e] * IND + NS + t], v);
        }
    }
    if (tid < EPB && e0 + tid < NE) atomicAdd(&g_cnt[sS[tid]], 1.f);
}

/* ---------------- epilogue ---------------- */
__global__ void k_pre(const float* __restrict__ na) {
    int i = blockIdx.x * blockDim.x + threadIdx.x, st = gridDim.x * blockDim.x;
    for (int x = i; x < NN * IND; x += st) {
        int n = x / IND;
        g_pre[x] = g_sum[x] / fmaxf(g_cnt[n], 1.f) + na[x];
    }
}

__global__ __launch_bounds__(256) void k_stat() {
    __shared__ float r1[256], r2[256];
    int b = blockIdx.x, tid = threadIdx.x;
    float s = 0.f, q = 0.f;
    if (b < NS) {
        for (int n = tid; n < NN; n += 256) { float v = g_pre[n * IND + b]; s += v; q += v * v; }
    } else {
        int i = b - NS;
        for (int n = tid; n < NN; n += 256) {
            const float* p = &g_pre[n * IND + NS + i * 3];
            s += p[0] * p[0] + p[1] * p[1] + p[2] * p[2];
        }
    }
    r1[tid] = s; r2[tid] = q; __syncthreads();
    for (int o = 128; o > 0; o >>= 1) {
        if (tid < o) { r1[tid] += r1[tid + o]; r2[tid] += r2[tid + o]; }
        __syncthreads();
    }
    if (tid == 0) {
        if (b < NS) { g_stat[b] = r1[0]; g_stat[NS + b] = r2[0]; }
        else g_stat[NS + b] = r1[0];
    }
}

__global__ void k_nrm(const float* __restrict__ bnw, const float* __restrict__ bnb) {
    int t = threadIdx.x;
    if (t < NS) {
        float mu = g_stat[t] * (1.f / NN);
        float var = g_stat[NS + t] * (1.f / NN) - mu * mu;
        float sc = bnw[t] * rsqrtf(var + EPSF);
        g_nrm[t] = sc; g_nrm[NS + t] = bnb[t] - mu * sc;
    } else if (t < NS + NV) {
        int i = t - NS;
        float fn = g_stat[2 * NS + i] * (1.f / (3.f * NN));
        g_nrm[2 * NS + i] = bnw[NS + i] * rsqrtf(fn + EPSF);
    }
}

__global__ void k_apply(float* __restrict__ out) {
    int i = blockIdx.x * blockDim.x + threadIdx.x, st = gridDim.x * blockDim.x;
    for (int x = i; x < NN * IND; x += st) {
        int n = x / IND, d = x - n * IND;
        out[x] = (d < NS) ? g_pre[x] * g_nrm[d] + g_nrm[NS + d]
                          : g_pre[x] * g_nrm[2 * NS + (d - NS) / 3];
    }
}

extern "C" void kernel_launch(void* const* d_in, const int* in_sizes, int n_in,
                              void* d_out, int out_size) {
    (void)in_sizes; (void)n_in; (void)out_size;
    const float* nattr = (const float*)d_in[0];
    const float* ea    = (const float*)d_in[1];
    const float* esh   = (const float*)d_in[2];
    const float* w1    = (const float*)d_in[3];
    const float* b1    = (const float*)d_in[4];
    const float* w2    = (const float*)d_in[5];
    const float* b2    = (const float*)d_in[6];
    const float* bnw   = (const float*)d_in[7];
    const float* bnb   = (const float*)d_in[8];
    const int*   ei    = (const int*)d_in[9];
    float* out = (float*)d_out;

    size_t sm1 = (size_t)(19008 + 20736) * 4;   /* 158,976 B */
    size_t sm2 = (size_t)49136 * 4;             /* 196,544 B */
    cudaFuncSetAttribute(k_fc1,  cudaFuncAttributeMaxDynamicSharedMemorySize, (int)sm1);
    cudaFuncSetAttribute(k_main, cudaFuncAttributeMaxDynamicSharedMemorySize, (int)sm2);

    k_zero<<<512, 256>>>();
    k_fc1<<<NBLK, 256, sm1>>>(ea, w1, b1);
    k_main<<<NBLK, 256, sm2>>>(nattr, esh, w2, b2, ei);
    k_pre<<<512, 256>>>(nattr);
    k_stat<<<NS + NV, 256>>>();
    k_nrm<<<1, 64>>>(bnw, bnb);
    k_apply<<<512, 256>>>(out);
}

// round 4
// speedup vs baseline: 1.5568x; 1.0912x over previous
#include <cuda_runtime.h>
#include <math.h>

#define NS 48
#define NV 10
#define NE 100000
#define NN 10000
#define NF 144
#define IND 78
#define WNUM 3364
#define EPB 128
#define NBLK ((NE + EPB - 1) / EPB)
#define NCHUNK 71
#define A_SS 0.102062072615966f   /* 1/sqrt(96) = a_ss = a_sv */
#define A_VV 0.223606797749979f   /* 1/sqrt(20) = a_vs = a_vv */
#define ISQ3 0.577350269189626f
#define EPSF 1e-5f

typedef unsigned long long u64;

/* packed f32x2 helpers (Blackwell) */
__device__ __forceinline__ u64 pk2(float x) {
    u64 r; asm("mov.b64 %0, {%1, %1};" : "=l"(r) : "f"(x)); return r;
}
__device__ __forceinline__ u64 f2fma(u64 a, u64 b, u64 c) {
    u64 d; asm("fma.rn.f32x2 %0, %1, %2, %3;" : "=l"(d) : "l"(a), "l"(b), "l"(c)); return d;
}
__device__ __forceinline__ u64 f2add(u64 a, u64 b) {
    u64 d; asm("add.rn.f32x2 %0, %1, %2;" : "=l"(d) : "l"(a), "l"(b)); return d;
}
__device__ __forceinline__ float2 upk2(u64 v) {
    float2 f; asm("mov.b64 {%0, %1}, %2;" : "=f"(f.x), "=f"(f.y) : "l"(v)); return f;
}

/* device scratch (no runtime allocation) */
__device__ float g_h[(size_t)NE * NF];
__device__ float g_sum[NN * IND];
__device__ float g_cnt[NN];
__device__ float g_pre[NN * IND];
__device__ float g_stat[2 * NS + NV];
__device__ float g_nrm[2 * NS + NV];

__global__ void k_zero() {
    int i = blockIdx.x * blockDim.x + threadIdx.x, st = gridDim.x * blockDim.x;
    for (int x = i; x < NN * IND; x += st) g_sum[x] = 0.f;
    for (int x = i; x < NN; x += st) g_cnt[x] = 0.f;
    if (i < 2 * NS + NV) g_stat[i] = 0.f;
}

/* ---------------- fc1 + relu -> g_h (packed f32x2) ---------------- */
__global__ __launch_bounds__(256, 1) void k_fc1(const float* __restrict__ ea,
                                                const float* __restrict__ w1,
                                                const float* __restrict__ b1) {
    extern __shared__ float sm[];
    float* sE = sm;            /* [144][132] transposed edge_attr tile */
    float* sW = sm + 19008;    /* [144][144] */
    int tid = threadIdx.x, tx = tid & 7, ty = tid >> 3;
    int e0 = blockIdx.x * EPB;

    for (int x = tid; x < EPB * NF; x += 256) {
        int e = x / NF, k = x - e * NF;
        sE[k * 132 + e] = (e0 + e < NE) ? ea[(size_t)(e0 + e) * NF + k] : 0.f;
    }
    for (int x = tid; x < NF * NF; x += 256) sW[x] = w1[x];
    __syncthreads();

    u64 acc2[4][9];
#pragma unroll
    for (int r = 0; r < 4; r++)
#pragma unroll
        for (int j = 0; j < 9; j++) acc2[r][j] = 0ULL;

    for (int k = 0; k < NF; k++) {
        float4 hv = *(const float4*)&sE[k * 132 + ty * 4];
        u64 h0 = pk2(hv.x), h1 = pk2(hv.y), h2 = pk2(hv.z), h3 = pk2(hv.w);
        const u64* wp = (const u64*)&sW[k * NF + tx * 18];
#pragma unroll
        for (int j = 0; j < 9; j++) {
            u64 wv = wp[j];
            acc2[0][j] = f2fma(h0, wv, acc2[0][j]);
            acc2[1][j] = f2fma(h1, wv, acc2[1][j]);
            acc2[2][j] = f2fma(h2, wv, acc2[2][j]);
            acc2[3][j] = f2fma(h3, wv, acc2[3][j]);
        }
    }
#pragma unroll
    for (int r = 0; r < 4; r++) {
        int e = e0 + ty * 4 + r;
        if (e < NE) {
#pragma unroll
            for (int j = 0; j < 9; j++) {
                int o = tx * 18 + 2 * j;
                float2 t = upk2(acc2[r][j]);
                g_h[(size_t)e * NF + o]     = fmaxf(t.x + b1[o], 0.f);
                g_h[(size_t)e * NF + o + 1] = fmaxf(t.y + b1[o + 1], 0.f);
            }
        }
    }
}

/* -------- fused fc2 + tensor product + scatter (packed f32x2) --------- */
/* 256 threads: tx 0..7 -> 6 cols (3 f32x2), ty 0..31 -> 4 edges          */
__global__ __launch_bounds__(256, 1) void k_main(const float* __restrict__ na,
                                                 const float* __restrict__ esh,
                                                 const float* __restrict__ w2,
                                                 const float* __restrict__ b2,
                                                 const int* __restrict__ ei) {
    extern __shared__ float sm[];
    float* sH  = sm;             /* [144][132] h tile (transposed)  19008 */
    float* sW  = sm + 19008;     /* [144][48] fc2 col chunk          6912 */
    float* sB  = sm + 25920;     /* [48] bias chunk                    48 */
    float* sCS = sm + 25968;     /* [128][58] combined out_s coeffs  7424 */
    float* sU  = sm + 33392;     /* [128][48] a_sv*xs                6144 */
    float* sV  = sm + 39536;     /* [128][30] a_vv*xv                3840 */
    float* s0  = sm + 43376;     /* [128]                             128 */
    float* s1  = sm + 43504;     /* [128][3]                          384 */
    int*   sS  = (int*)(sm + 43888); /* [128] src node                128 */
    float* aP  = sm + 44016;     /* [128][10]                        1280 */
    float* aQ  = sm + 45296;     /* [128][30]                        3840 */
    int tid = threadIdx.x, tx = tid & 7, ty = tid >> 3;
    int e0 = blockIdx.x * EPB;

    for (int x = tid; x < EPB * NF; x += 256) {
        int e = x / NF, k = x - e * NF;
        sH[k * 132 + e] = (e0 + e < NE) ? g_h[(size_t)(e0 + e) * NF + k] : 0.f;
    }
    for (int x = tid; x < EPB * IND; x += 256) {
        int e = x / IND, d = x - e * IND;
        float v = 0.f;
        if (e0 + e < NE) { int dst = ei[NE + e0 + e]; v = na[dst * IND + d]; }
        if (d < NS) sU[e * NS + d] = A_SS * v;
        else        sV[e * 30 + d - NS] = A_VV * v;
    }
    if (tid < EPB) {
        int eg = e0 + tid;
        if (eg < NE) {
            sS[tid] = ei[eg]; s0[tid] = esh[eg * 4];
            s1[tid * 3] = esh[eg * 4 + 1]; s1[tid * 3 + 1] = esh[eg * 4 + 2];
            s1[tid * 3 + 2] = esh[eg * 4 + 3];
        } else {
            sS[tid] = 0; s0[tid] = 0.f;
            s1[tid * 3] = s1[tid * 3 + 1] = s1[tid * 3 + 2] = 0.f;
        }
    }
    for (int x = tid; x < EPB * 40; x += 256) aP[x] = 0.f;  /* aP,aQ contiguous */
    __syncthreads();
    for (int x = tid; x < EPB * 58; x += 256) {
        int e = x / 58, i = x - e * 58;
        if (i < 48) sCS[x] = s0[e] * sU[e * 48 + i];
        else {
            int ii = i - 48;
            sCS[x] = ISQ3 * (sV[e * 30 + ii * 3] * s1[e * 3] +
                             sV[e * 30 + ii * 3 + 1] * s1[e * 3 + 1] +
                             sV[e * 30 + ii * 3 + 2] * s1[e * 3 + 2]);
        }
    }
    __syncthreads();

    u64 acc2[4][3];
#pragma unroll
    for (int r = 0; r < 4; r++)
#pragma unroll
        for (int p = 0; p < 3; p++) acc2[r][p] = 0ULL;

    for (int ch = 0; ch < NCHUNK; ch++) {
        int c0 = ch * 48;
        if (ch < 70) {
            for (int x = tid; x < NF * 12; x += 256) {
                int k = x / 12, q = x - k * 12;
                *(float4*)&sW[k * 48 + q * 4] =
                    *(const float4*)&w2[(size_t)k * WNUM + c0 + q * 4];
            }
            if (tid < 48) sB[tid] = b2[c0 + tid];
        } else {
            for (int x = tid; x < NF * 12; x += 256) {
                int k = x / 12, q = x - k * 12;
                int gc = c0 + q * 4;
                float4 v = make_float4(0.f, 0.f, 0.f, 0.f);
                if (gc + 3 < WNUM) v = *(const float4*)&w2[(size_t)k * WNUM + gc];
                *(float4*)&sW[k * 48 + q * 4] = v;
            }
            if (tid < 48) sB[tid] = (c0 + tid < WNUM) ? b2[c0 + tid] : 0.f;
        }
        __syncthreads();

        u64 wr2[4][3];
#pragma unroll
        for (int r = 0; r < 4; r++)
#pragma unroll
            for (int p = 0; p < 3; p++) wr2[r][p] = 0ULL;

#pragma unroll 4
        for (int k = 0; k < NF; k++) {
            float4 hv = *(const float4*)&sH[k * 132 + ty * 4];
            u64 h0 = pk2(hv.x), h1 = pk2(hv.y), h2 = pk2(hv.z), h3 = pk2(hv.w);
            const u64* wp = (const u64*)&sW[k * 48 + tx * 6];
            u64 w0 = wp[0], w1v = wp[1], w2v = wp[2];
            wr2[0][0] = f2fma(h0, w0, wr2[0][0]);
            wr2[0][1] = f2fma(h0, w1v, wr2[0][1]);
            wr2[0][2] = f2fma(h0, w2v, wr2[0][2]);
            wr2[1][0] = f2fma(h1, w0, wr2[1][0]);
            wr2[1][1] = f2fma(h1, w1v, wr2[1][1]);
            wr2[1][2] = f2fma(h1, w2v, wr2[1][2]);
            wr2[2][0] = f2fma(h2, w0, wr2[2][0]);
            wr2[2][1] = f2fma(h2, w1v, wr2[2][1]);
            wr2[2][2] = f2fma(h2, w2v, wr2[2][2]);
            wr2[3][0] = f2fma(h3, w0, wr2[3][0]);
            wr2[3][1] = f2fma(h3, w1v, wr2[3][1]);
            wr2[3][2] = f2fma(h3, w2v, wr2[3][2]);
        }

        const u64* bp = (const u64*)&sB[tx * 6];
        u64 bb0 = bp[0], bb1 = bp[1], bb2v = bp[2];

        if (ch < 58) {
#pragma unroll
            for (int r = 0; r < 4; r++) {
                u64 cf = pk2(sCS[(ty * 4 + r) * 58 + ch]);
                acc2[r][0] = f2fma(cf, f2add(wr2[r][0], bb0), acc2[r][0]);
                acc2[r][1] = f2fma(cf, f2add(wr2[r][1], bb1), acc2[r][1]);
                acc2[r][2] = f2fma(cf, f2add(wr2[r][2], bb2v), acc2[r][2]);
            }
        } else {
            float wr[4][6];
#pragma unroll
            for (int r = 0; r < 4; r++) {
                float2 t0 = upk2(f2add(wr2[r][0], bb0));
                float2 t1 = upk2(f2add(wr2[r][1], bb1));
                float2 t2 = upk2(f2add(wr2[r][2], bb2v));
                wr[r][0] = t0.x; wr[r][1] = t0.y; wr[r][2] = t1.x;
                wr[r][3] = t1.y; wr[r][4] = t2.x; wr[r][5] = t2.y;
            }
            if (ch < 68) {
#pragma unroll
                for (int j = 0; j < 6; j++) {
                    int tt = (ch - 58) * 48 + tx * 6 + j;
                    int i = tt / 10, o = tt - i * 10;
#pragma unroll
                    for (int r = 0; r < 4; r++) {
                        int e = ty * 4 + r;
                        atomicAdd(&aP[e * 10 + o], sU[e * 48 + i] * wr[r][j]);
                    }
                }
            } else {
#pragma unroll
                for (int j = 0; j < 6; j++) {
                    int tt = (ch - 68) * 48 + tx * 6 + j;
                    if (tt < 100) {
                        int i = tt / 10, o = tt - i * 10;
#pragma unroll
                        for (int r = 0; r < 4; r++) {
                            int e = ty * 4 + r;
                            float w = wr[r][j];
                            atomicAdd(&aQ[e * 30 + o * 3],     sV[e * 30 + i * 3] * w);
                            atomicAdd(&aQ[e * 30 + o * 3 + 1], sV[e * 30 + i * 3 + 1] * w);
                            atomicAdd(&aQ[e * 30 + o * 3 + 2], sV[e * 30 + i * 3 + 2] * w);
                        }
                    }
                }
            }
        }
        __syncthreads();
    }

    /* scatter out_s straight from registers */
#pragma unroll
    for (int r = 0; r < 4; r++) {
        int e = ty * 4 + r;
        if (e0 + e < NE) {
            int base = sS[e] * IND + tx * 6;
#pragma unroll
            for (int p = 0; p < 3; p++) {
                float2 t = upk2(acc2[r][p]);
                atomicAdd(&g_sum[base + 2 * p], t.x);
                atomicAdd(&g_sum[base + 2 * p + 1], t.y);
            }
        }
    }
    for (int x = tid; x < EPB * 30; x += 256) {
        int e = x / 30, t = x - e * 30, o = t / 3, cc = t - o * 3;
        if (e0 + e < NE) {
            float v = s1[e * 3 + cc] * aP[e * 10 + o] + s0[e] * aQ[e * 30 + t];
            atomicAdd(&g_sum[sS[e] * IND + NS + t], v);
        }
    }
    if (tid < EPB && e0 + tid < NE) atomicAdd(&g_cnt[sS[tid]], 1.f);
}

/* ---------------- epilogue ---------------- */
__global__ void k_pre(const float* __restrict__ na) {
    int i = blockIdx.x * blockDim.x + threadIdx.x, st = gridDim.x * blockDim.x;
    for (int x = i; x < NN * IND; x += st) {
        int n = x / IND;
        g_pre[x] = g_sum[x] / fmaxf(g_cnt[n], 1.f) + na[x];
    }
}

__global__ __launch_bounds__(256) void k_stat() {
    __shared__ float r1[256], r2[256];
    int b = blockIdx.x, tid = threadIdx.x;
    float s = 0.f, q = 0.f;
    if (b < NS) {
        for (int n = tid; n < NN; n += 256) { float v = g_pre[n * IND + b]; s += v; q += v * v; }
    } else {
        int i = b - NS;
        for (int n = tid; n < NN; n += 256) {
            const float* p = &g_pre[n * IND + NS + i * 3];
            s += p[0] * p[0] + p[1] * p[1] + p[2] * p[2];
        }
    }
    r1[tid] = s; r2[tid] = q; __syncthreads();
    for (int o = 128; o > 0; o >>= 1) {
        if (tid < o) { r1[tid] += r1[tid + o]; r2[tid] += r2[tid + o]; }
        __syncthreads();
    }
    if (tid == 0) {
        if (b < NS) { g_stat[b] = r1[0]; g_stat[NS + b] = r2[0]; }
        else g_stat[NS + b] = r1[0];
    }
}

__global__ void k_nrm(const float* __restrict__ bnw, const float* __restrict__ bnb) {
    int t = threadIdx.x;
    if (t < NS) {
        float mu = g_stat[t] * (1.f / NN);
        float var = g_stat[NS + t] * (1.f / NN) - mu * mu;
        float sc = bnw[t] * rsqrtf(var + EPSF);
        g_nrm[t] = sc; g_nrm[NS + t] = bnb[t] - mu * sc;
    } else if (t < NS + NV) {
        int i = t - NS;
        float fn = g_stat[2 * NS + i] * (1.f / (3.f * NN));
        g_nrm[2 * NS + i] = bnw[NS + i] * rsqrtf(fn + EPSF);
    }
}

__global__ void k_apply(float* __restrict__ out) {
    int i = blockIdx.x * blockDim.x + threadIdx.x, st = gridDim.x * blockDim.x;
    for (int x = i; x < NN * IND; x += st) {
        int n = x / IND, d = x - n * IND;
        out[x] = (d < NS) ? g_pre[x] * g_nrm[d] + g_nrm[NS + d]
                          : g_pre[x] * g_nrm[2 * NS + (d - NS) / 3];
    }
}

extern "C" void kernel_launch(void* const* d_in, const int* in_sizes, int n_in,
                              void* d_out, int out_size) {
    (void)in_sizes; (void)n_in; (void)out_size;
    const float* nattr = (const float*)d_in[0];
    const float* ea    = (const float*)d_in[1];
    const float* esh   = (const float*)d_in[2];
    const float* w1    = (const float*)d_in[3];
    const float* b1    = (const float*)d_in[4];
    const float* w2    = (const float*)d_in[5];
    const float* b2    = (const float*)d_in[6];
    const float* bnw   = (const float*)d_in[7];
    const float* bnb   = (const float*)d_in[8];
    const int*   ei    = (const int*)d_in[9];
    float* out = (float*)d_out;

    size_t sm1 = (size_t)(19008 + 20736) * 4;   /* 158,976 B */
    size_t sm2 = (size_t)49136 * 4;             /* 196,544 B */
    cudaFuncSetAttribute(k_fc1,  cudaFuncAttributeMaxDynamicSharedMemorySize, (int)sm1);
    cudaFuncSetAttribute(k_main, cudaFuncAttributeMaxDynamicSharedMemorySize, (int)sm2);

    k_zero<<<512, 256>>>();
    k_fc1<<<NBLK, 256, sm1>>>(ea, w1, b1);
    k_main<<<NBLK, 256, sm2>>>(nattr, esh, w2, b2, ei);
    k_pre<<<512, 256>>>(nattr);
    k_stat<<<NS + NV, 256>>>();
    k_nrm<<<1, 64>>>(bnw, bnb);
    k_apply<<<512, 256>>>(out);
}

// round 6
// speedup vs baseline: 2.7883x; 1.7911x over previous
#include <cuda_runtime.h>
#include <cuda_bf16.h>
#include <stdint.h>
#include <math.h>

#define NS 48
#define NV 10
#define NE 100000
#define NN 10000
#define NF 144
#define IND 78
#define WNUM 3364
#define EPB 128
#define NBLK ((NE + EPB - 1) / EPB)
#define NCH 71
#define A_SS 0.102062072615966f
#define A_VV 0.223606797749979f
#define ISQ3 0.577350269189626f
#define EPSF 1e-5f

/* ---- SMEM byte offsets (k_main) ---- */
#define OFF_AHI 0           /* [128][152] bf16 = 38912 */
#define OFF_ALO 38912
#define OFF_BHI 77824       /* [144][56] bf16 = 16128 */
#define OFF_BLO 93952
#define OFF_BIAS 110080     /* [48] f32 */
#define OFF_CS  110272      /* [128][58] f32 */
#define OFF_U   139968      /* [128][48] f32 */
#define OFF_V   164544      /* [128][30] f32 */
#define OFF_S0  179904      /* [128] f32 */
#define OFF_S1  180416      /* [128][3] f32 */
#define OFF_SS  181952      /* [128] int */
#define OFF_AP  182464      /* [128][10] f32 */
#define OFF_AQ  187584      /* [128][30] f32 */
#define SMEMTOT 202944

__device__ float g_h[(size_t)NE * NF];
__device__ __nv_bfloat16 g_whl[(size_t)NCH * NF * 96];  /* per chunk: [144][48hi|48lo] */
__device__ float g_sum[NN * IND];
__device__ float g_cnt[NN];
__device__ float g_pre[NN * IND];
__device__ float g_stat[2 * NS + NV];
__device__ float g_nrm[2 * NS + NV];

__device__ __forceinline__ uint32_t smem_u32(const void* p) {
    uint32_t a;
    asm("{ .reg .u64 t; cvta.to.shared.u64 t, %1; cvt.u32.u64 %0, t; }" : "=r"(a) : "l"(p));
    return a;
}
__device__ __forceinline__ void ldsm4(uint32_t* r, uint32_t a) {
    asm volatile("ldmatrix.sync.aligned.m8n8.x4.shared.b16 {%0,%1,%2,%3}, [%4];"
                 : "=r"(r[0]), "=r"(r[1]), "=r"(r[2]), "=r"(r[3]) : "r"(a));
}
__device__ __forceinline__ void ldsm4t(uint32_t* r, uint32_t a) {
    asm volatile("ldmatrix.sync.aligned.m8n8.x4.trans.shared.b16 {%0,%1,%2,%3}, [%4];"
                 : "=r"(r[0]), "=r"(r[1]), "=r"(r[2]), "=r"(r[3]) : "r"(a));
}
__device__ __forceinline__ void mma16816(float* d, const uint32_t* a,
                                         uint32_t b0, uint32_t b1) {
    asm volatile("mma.sync.aligned.m16n8k16.row.col.f32.bf16.bf16.f32 "
                 "{%0,%1,%2,%3}, {%4,%5,%6,%7}, {%8,%9}, {%0,%1,%2,%3};"
                 : "+f"(d[0]), "+f"(d[1]), "+f"(d[2]), "+f"(d[3])
                 : "r"(a[0]), "r"(a[1]), "r"(a[2]), "r"(a[3]), "r"(b0), "r"(b1));
}

/* -------- w2 -> bf16 hi/lo chunk blob -------- */
__global__ void k_wprep(const float* __restrict__ w2) {
    int x = blockIdx.x * blockDim.x + threadIdx.x;
    if (x < NCH * NF * 48) {
        int n = x % 48, t = x / 48, k = t % NF, ch = t / NF;
        int gc = ch * 48 + n;
        float v = (gc < WNUM) ? w2[(size_t)k * WNUM + gc] : 0.f;
        __nv_bfloat16 hb = __float2bfloat16_rn(v);
        __nv_bfloat16 lb = __float2bfloat16_rn(v - __bfloat162float(hb));
        size_t base = (size_t)(ch * NF + k) * 96;
        g_whl[base + n] = hb;
        g_whl[base + 48 + n] = lb;
    }
}

/* ---------------- fc1 + relu -> g_h (proven FFMA) ---------------- */
__global__ __launch_bounds__(256, 1) void k_fc1(const float* __restrict__ ea,
                                                const float* __restrict__ w1,
                                                const float* __restrict__ b1) {
    extern __shared__ float sm[];
    float* sE = sm;            /* [144][132] */
    float* sW = sm + 19008;    /* [144][144] */
    int tid = threadIdx.x, tx = tid & 7, ty = tid >> 3;
    int e0 = blockIdx.x * EPB;

    for (int x = tid; x < EPB * NF; x += 256) {
        int e = x / NF, k = x - e * NF;
        sE[k * 132 + e] = (e0 + e < NE) ? ea[(size_t)(e0 + e) * NF + k] : 0.f;
    }
    for (int x = tid; x < NF * NF; x += 256) sW[x] = w1[x];
    __syncthreads();

    float acc[4][18];
#pragma unroll
    for (int r = 0; r < 4; r++)
#pragma unroll
        for (int j = 0; j < 18; j++) acc[r][j] = 0.f;

    for (int k = 0; k < NF; k++) {
        float4 hv = *(const float4*)&sE[k * 132 + ty * 4];
        float wv[18];
#pragma unroll
        for (int j = 0; j < 18; j++) wv[j] = sW[k * NF + tx * 18 + j];
#pragma unroll
        for (int j = 0; j < 18; j++) {
            acc[0][j] = fmaf(hv.x, wv[j], acc[0][j]);
            acc[1][j] = fmaf(hv.y, wv[j], acc[1][j]);
            acc[2][j] = fmaf(hv.z, wv[j], acc[2][j]);
            acc[3][j] = fmaf(hv.w, wv[j], acc[3][j]);
        }
    }
#pragma unroll
    for (int r = 0; r < 4; r++) {
        int e = e0 + ty * 4 + r;
        if (e < NE) {
#pragma unroll
            for (int j = 0; j < 18; j++) {
                int o = tx * 18 + j;
                g_h[(size_t)e * NF + o] = fmaxf(acc[r][j] + b1[o], 0.f);
            }
        }
    }
}

/* -------- fused fc2 (mma.sync bf16 3-product) + tensor product + scatter -------- */
__global__ __launch_bounds__(256, 1) void k_main(const float* __restrict__ na,
                                                 const float* __restrict__ esh,
                                                 const float* __restrict__ b2,
                                                 const int* __restrict__ ei) {
    extern __shared__ char smc[];
    uint32_t smb = smem_u32(smc);
    __nv_bfloat16* sAhi = (__nv_bfloat16*)(smc + OFF_AHI);
    __nv_bfloat16* sAlo = (__nv_bfloat16*)(smc + OFF_ALO);
    float* sB  = (float*)(smc + OFF_BIAS);
    float* sCS = (float*)(smc + OFF_CS);
    float* sU  = (float*)(smc + OFF_U);
    float* sV  = (float*)(smc + OFF_V);
    float* s0  = (float*)(smc + OFF_S0);
    float* s1  = (float*)(smc + OFF_S1);
    int*   sS  = (int*)(smc + OFF_SS);
    float* aP  = (float*)(smc + OFF_AP);
    float* aQ  = (float*)(smc + OFF_AQ);

    int tid = threadIdx.x, lane = tid & 31, warp = tid >> 5;
    int gid = lane >> 2, tig = lane & 3;
    int e0 = blockIdx.x * EPB;
    int er0 = warp * 16 + gid, er1 = er0 + 8;

    /* A tile: g_h -> bf16 hi/lo, row stride 152 */
    for (int x = tid; x < EPB * NF; x += 256) {
        int e = x / NF, k = x - e * NF;
        float v = (e0 + e < NE) ? g_h[(size_t)(e0 + e) * NF + k] : 0.f;
        __nv_bfloat16 hb = __float2bfloat16_rn(v);
        sAhi[e * 152 + k] = hb;
        sAlo[e * 152 + k] = __float2bfloat16_rn(v - __bfloat162float(hb));
    }
    for (int x = tid; x < EPB * IND; x += 256) {
        int e = x / IND, d = x - e * IND;
        float v = 0.f;
        if (e0 + e < NE) { int dst = ei[NE + e0 + e]; v = na[dst * IND + d]; }
        if (d < NS) sU[e * NS + d] = A_SS * v;
        else        sV[e * 30 + d - NS] = A_VV * v;
    }
    if (tid < EPB) {
        int eg = e0 + tid;
        if (eg < NE) {
            sS[tid] = ei[eg]; s0[tid] = esh[eg * 4];
            s1[tid * 3] = esh[eg * 4 + 1]; s1[tid * 3 + 1] = esh[eg * 4 + 2];
            s1[tid * 3 + 2] = esh[eg * 4 + 3];
        } else {
            sS[tid] = 0; s0[tid] = 0.f;
            s1[tid * 3] = s1[tid * 3 + 1] = s1[tid * 3 + 2] = 0.f;
        }
    }
    for (int x = tid; x < EPB * 40; x += 256) aP[x] = 0.f;  /* aP,aQ contiguous */
    __syncthreads();
    for (int x = tid; x < EPB * 58; x += 256) {
        int e = x / 58, i = x - e * 58;
        if (i < 48) sCS[x] = s0[e] * sU[e * 48 + i];
        else {
            int ii = i - 48;
            sCS[x] = ISQ3 * (sV[e * 30 + ii * 3] * s1[e * 3] +
                             sV[e * 30 + ii * 3 + 1] * s1[e * 3 + 1] +
                             sV[e * 30 + ii * 3 + 2] * s1[e * 3 + 2]);
        }
    }

    /* ldmatrix base addresses */
    uint32_t aHiA = smb + OFF_AHI + ((warp * 16 + (lane & 15)) * 152 + (lane >> 4) * 8) * 2;
    uint32_t aLoA = aHiA + (OFF_ALO - OFF_AHI);
    uint32_t bHiA = smb + OFF_BHI + ((lane & 15) * 56 + (lane >> 4) * 8) * 2;
    uint32_t bLoA = bHiA + (OFF_BLO - OFF_BHI);

    float acc[6][4];
#pragma unroll
    for (int nt = 0; nt < 6; nt++)
#pragma unroll
        for (int q = 0; q < 4; q++) acc[nt][q] = 0.f;

    for (int cc = 0; cc < NCH; cc++) {
        __syncthreads();   /* previous chunk's B smem reads done */
        {
            const uint4* src = (const uint4*)(g_whl + (size_t)cc * NF * 96);
            for (int x = tid; x < 1728; x += 256) {
                int k = x / 12, part = x - k * 12;
                uint4 v = src[x];
                char* dst = smc + (part < 6 ? OFF_BHI : OFF_BLO)
                          + k * 112 + (part % 6) * 16;
                *(uint4*)dst = v;
            }
            if (tid < 48) sB[tid] = (cc * 48 + tid < WNUM) ? b2[cc * 48 + tid] : 0.f;
        }
        __syncthreads();

        float d[6][4];
#pragma unroll
        for (int nt = 0; nt < 6; nt++)
#pragma unroll
            for (int q = 0; q < 4; q++) d[nt][q] = 0.f;

#pragma unroll
        for (int kt = 0; kt < 9; kt++) {
            uint32_t AH[4], AL[4];
            ldsm4(AH, aHiA + kt * 32);
            ldsm4(AL, aLoA + kt * 32);
#pragma unroll
            for (int nt2 = 0; nt2 < 3; nt2++) {
                uint32_t BH[4], BL[4];
                ldsm4t(BH, bHiA + kt * 1792 + nt2 * 32);
                ldsm4t(BL, bLoA + kt * 1792 + nt2 * 32);
                mma16816(d[2 * nt2], AH, BH[0], BH[1]);
                mma16816(d[2 * nt2], AH, BL[0], BL[1]);
                mma16816(d[2 * nt2], AL, BH[0], BH[1]);
                mma16816(d[2 * nt2 + 1], AH, BH[2], BH[3]);
                mma16816(d[2 * nt2 + 1], AH, BL[2], BL[3]);
                mma16816(d[2 * nt2 + 1], AL, BH[2], BH[3]);
            }
        }

        /* consume */
        if (cc < 58) {
            float cf0 = sCS[er0 * 58 + cc], cf1 = sCS[er1 * 58 + cc];
#pragma unroll
            for (int nt = 0; nt < 6; nt++) {
                int col = nt * 8 + tig * 2;
                float b0 = sB[col], b1v = sB[col + 1];
                acc[nt][0] = fmaf(cf0, d[nt][0] + b0, acc[nt][0]);
                acc[nt][1] = fmaf(cf0, d[nt][1] + b1v, acc[nt][1]);
                acc[nt][2] = fmaf(cf1, d[nt][2] + b0, acc[nt][2]);
                acc[nt][3] = fmaf(cf1, d[nt][3] + b1v, acc[nt][3]);
            }
        } else if (cc < 68) {
#pragma unroll
            for (int nt = 0; nt < 6; nt++) {
#pragma unroll
                for (int j = 0; j < 2; j++) {
                    int col = nt * 8 + tig * 2 + j;
                    int tt = (cc - 58) * 48 + col;
                    int i = tt / 10, o = tt - i * 10;
                    float bb = sB[col];
                    atomicAdd(&aP[er0 * 10 + o], sU[er0 * 48 + i] * (d[nt][j] + bb));
                    atomicAdd(&aP[er1 * 10 + o], sU[er1 * 48 + i] * (d[nt][2 + j] + bb));
                }
            }
        } else {
#pragma unroll
            for (int nt = 0; nt < 6; nt++) {
#pragma unroll
                for (int j = 0; j < 2; j++) {
                    int col = nt * 8 + tig * 2 + j;
                    int tt = (cc - 68) * 48 + col;
                    if (tt < 100) {
                        int i = tt / 10, o = tt - i * 10;
                        float bb = sB[col];
                        float w0 = d[nt][j] + bb, w1v = d[nt][2 + j] + bb;
                        const float* vp0 = &sV[er0 * 30 + i * 3];
                        const float* vp1 = &sV[er1 * 30 + i * 3];
                        atomicAdd(&aQ[er0 * 30 + o * 3],     vp0[0] * w0);
                        atomicAdd(&aQ[er0 * 30 + o * 3 + 1], vp0[1] * w0);
                        atomicAdd(&aQ[er0 * 30 + o * 3 + 2], vp0[2] * w0);
                        atomicAdd(&aQ[er1 * 30 + o * 3],     vp1[0] * w1v);
                        atomicAdd(&aQ[er1 * 30 + o * 3 + 1], vp1[1] * w1v);
                        atomicAdd(&aQ[er1 * 30 + o * 3 + 2], vp1[2] * w1v);
                    }
                }
            }
        }
    }
    __syncthreads();

    /* scatter out_s fragments */
    {
        int eg0 = e0 + er0, eg1 = e0 + er1;
        int b0v = sS[er0] * IND, b1v = sS[er1] * IND;
#pragma unroll
        for (int nt = 0; nt < 6; nt++) {
#pragma unroll
            for (int j = 0; j < 2; j++) {
                int col = nt * 8 + tig * 2 + j;
                if (eg0 < NE) atomicAdd(&g_sum[b0v + col], acc[nt][j]);
                if (eg1 < NE) atomicAdd(&g_sum[b1v + col], acc[nt][2 + j]);
            }
        }
    }
    /* vector part */
    for (int x = tid; x < EPB * 30; x += 256) {
        int e = x / 30, t = x - e * 30, o = t / 3, ccp = t - o * 3;
        if (e0 + e < NE) {
            float v = s1[e * 3 + ccp] * aP[e * 10 + o] + s0[e] * aQ[e * 30 + t];
            atomicAdd(&g_sum[sS[e] * IND + NS + t], v);
        }
    }
    if (tid < EPB && e0 + tid < NE) atomicAdd(&g_cnt[sS[tid]], 1.f);
}

/* ---------------- epilogue ---------------- */
__global__ void k_zero() {
    int i = blockIdx.x * blockDim.x + threadIdx.x, st = gridDim.x * blockDim.x;
    for (int x = i; x < NN * IND; x += st) g_sum[x] = 0.f;
    for (int x = i; x < NN; x += st) g_cnt[x] = 0.f;
    if (i < 2 * NS + NV) g_stat[i] = 0.f;
}
__global__ void k_pre(const float* __restrict__ na) {
    int i = blockIdx.x * blockDim.x + threadIdx.x, st = gridDim.x * blockDim.x;
    for (int x = i; x < NN * IND; x += st) {
        int n = x / IND;
        g_pre[x] = g_sum[x] / fmaxf(g_cnt[n], 1.f) + na[x];
    }
}
__global__ __launch_bounds__(256) void k_stat() {
    __shared__ float r1[256], r2[256];
    int b = blockIdx.x, tid = threadIdx.x;
    float s = 0.f, q = 0.f;
    if (b < NS) {
        for (int n = tid; n < NN; n += 256) { float v = g_pre[n * IND + b]; s += v; q += v * v; }
    } else {
        int i = b - NS;
        for (int n = tid; n < NN; n += 256) {
            const float* p = &g_pre[n * IND + NS + i * 3];
            s += p[0] * p[0] + p[1] * p[1] + p[2] * p[2];
        }
    }
    r1[tid] = s; r2[tid] = q; __syncthreads();
    for (int o = 128; o > 0; o >>= 1) {
        if (tid < o) { r1[tid] += r1[tid + o]; r2[tid] += r2[tid + o]; }
        __syncthreads();
    }
    if (tid == 0) {
        if (b < NS) { g_stat[b] = r1[0]; g_stat[NS + b] = r2[0]; }
        else g_stat[NS + b] = r1[0];
    }
}
__global__ void k_nrm(const float* __restrict__ bnw, const float* __restrict__ bnb) {
    int t = threadIdx.x;
    if (t < NS) {
        float mu = g_stat[t] * (1.f / NN);
        float var = g_stat[NS + t] * (1.f / NN) - mu * mu;
        float sc = bnw[t] * rsqrtf(var + EPSF);
        g_nrm[t] = sc; g_nrm[NS + t] = bnb[t] - mu * sc;
    } else if (t < NS + NV) {
        int i = t - NS;
        float fn = g_stat[2 * NS + i] * (1.f / (3.f * NN));
        g_nrm[2 * NS + i] = bnw[NS + i] * rsqrtf(fn + EPSF);
    }
}
__global__ void k_apply(float* __restrict__ out) {
    int i = blockIdx.x * blockDim.x + threadIdx.x, st = gridDim.x * blockDim.x;
    for (int x = i; x < NN * IND; x += st) {
        int n = x / IND, d = x - n * IND;
        out[x] = (d < NS) ? g_pre[x] * g_nrm[d] + g_nrm[NS + d]
                          : g_pre[x] * g_nrm[2 * NS + (d - NS) / 3];
    }
}

extern "C" void kernel_launch(void* const* d_in, const int* in_sizes, int n_in,
                              void* d_out, int out_size) {
    (void)in_sizes; (void)n_in; (void)out_size;
    const float* nattr = (const float*)d_in[0];
    const float* ea    = (const float*)d_in[1];
    const float* esh   = (const float*)d_in[2];
    const float* w1    = (const float*)d_in[3];
    const float* b1    = (const float*)d_in[4];
    const float* w2    = (const float*)d_in[5];
    const float* b2    = (const float*)d_in[6];
    const float* bnw   = (const float*)d_in[7];
    const float* bnb   = (const float*)d_in[8];
    const int*   ei    = (const int*)d_in[9];
    float* out = (float*)d_out;

    size_t sm1 = (size_t)(19008 + 20736) * 4;
    cudaFuncSetAttribute(k_fc1,  cudaFuncAttributeMaxDynamicSharedMemorySize, (int)sm1);
    cudaFuncSetAttribute(k_main, cudaFuncAttributeMaxDynamicSharedMemorySize, SMEMTOT);

    k_zero<<<512, 256>>>();
    k_wprep<<<(NCH * NF * 48 + 255) / 256, 256>>>(w2);
    k_fc1<<<NBLK, 256, sm1>>>(ea, w1, b1);
    k_main<<<NBLK, 256, SMEMTOT>>>(nattr, esh, b2, ei);
    k_pre<<<512, 256>>>(nattr);
    k_stat<<<NS + NV, 256>>>();
    k_nrm<<<1, 64>>>(bnw, bnb);
    k_apply<<<512, 256>>>(out);
}

// round 7
// speedup vs baseline: 3.7813x; 1.3561x over previous
#include <cuda_runtime.h>
#include <cuda_bf16.h>
#include <stdint.h>
#include <math.h>

#define NS 48
#define NV 10
#define NE 100000
#define NN 10000
#define NF 144
#define IND 78
#define WNUM 3364
#define EPB 128
#define NBLK ((NE + EPB - 1) / EPB)
#define NCH 71
#define A_SS 0.102062072615966f
#define A_VV 0.223606797749979f
#define ISQ3 0.577350269189626f
#define EPSF 1e-5f

/* ---- SMEM byte offsets (k_main) ---- */
#define OFF_B   0           /* [2 buf][hi 16128 | lo 16128] = 64512 */
#define OFF_CS  64512       /* [128][58] f32 = 29696 */
#define OFF_U   94208       /* [128][48] f32 = 24576 */
#define OFF_V   118784      /* [128][30] f32 = 15360 */
#define OFF_S0  134144      /* [128] f32 */
#define OFF_S1  134656      /* [128][3] f32 */
#define OFF_SS  136192      /* [128] int */
#define OFF_AP  136704      /* [128][10] f32 */
#define OFF_AQ  141824      /* [128][30] f32 */
#define SMEMTOT 157184

__device__ float g_h[(size_t)NE * NF];
__device__ __nv_bfloat16 g_whl[(size_t)NCH * NF * 96];  /* per chunk: [144][48hi|48lo] */
__device__ float g_sum[NN * IND];
__device__ float g_cnt[NN];
__device__ float g_pre[NN * IND];
__device__ float g_stat[2 * NS + NV];
__device__ float g_nrm[2 * NS + NV];

__device__ __forceinline__ uint32_t smem_u32(const void* p) {
    uint32_t a;
    asm("{ .reg .u64 t; cvta.to.shared.u64 t, %1; cvt.u32.u64 %0, t; }" : "=r"(a) : "l"(p));
    return a;
}
__device__ __forceinline__ void ldsm4t(uint32_t* r, uint32_t a) {
    asm volatile("ldmatrix.sync.aligned.m8n8.x4.trans.shared.b16 {%0,%1,%2,%3}, [%4];"
                 : "=r"(r[0]), "=r"(r[1]), "=r"(r[2]), "=r"(r[3]) : "r"(a));
}
__device__ __forceinline__ void ldsm2t(uint32_t* r, uint32_t a) {
    asm volatile("ldmatrix.sync.aligned.m8n8.x2.trans.shared.b16 {%0,%1}, [%2];"
                 : "=r"(r[0]), "=r"(r[1]) : "r"(a));
}
__device__ __forceinline__ void mma16816(float* d, const uint32_t* a,
                                         uint32_t b0, uint32_t b1) {
    asm volatile("mma.sync.aligned.m16n8k16.row.col.f32.bf16.bf16.f32 "
                 "{%0,%1,%2,%3}, {%4,%5,%6,%7}, {%8,%9}, {%0,%1,%2,%3};"
                 : "+f"(d[0]), "+f"(d[1]), "+f"(d[2]), "+f"(d[3])
                 : "r"(a[0]), "r"(a[1]), "r"(a[2]), "r"(a[3]), "r"(b0), "r"(b1));
}
__device__ __forceinline__ void cpa16(uint32_t dst, const void* src) {
    asm volatile("cp.async.cg.shared.global [%0], [%1], 16;" :: "r"(dst), "l"(src));
}
#define CPA_COMMIT() asm volatile("cp.async.commit_group;" ::: "memory")
#define CPA_WAIT0()  asm volatile("cp.async.wait_group 0;" ::: "memory")
__device__ __forceinline__ uint32_t pkbf(float x0, float x1) {
    unsigned short a = __bfloat16_as_ushort(__float2bfloat16_rn(x0));
    unsigned short b = __bfloat16_as_ushort(__float2bfloat16_rn(x1));
    return (uint32_t)a | ((uint32_t)b << 16);
}

/* -------- w2 -> bf16 hi/lo chunk blob -------- */
__global__ void k_wprep(const float* __restrict__ w2) {
    int x = blockIdx.x * blockDim.x + threadIdx.x;
    if (x < NCH * NF * 48) {
        int n = x % 48, t = x / 48, k = t % NF, ch = t / NF;
        int gc = ch * 48 + n;
        float v = (gc < WNUM) ? w2[(size_t)k * WNUM + gc] : 0.f;
        __nv_bfloat16 hb = __float2bfloat16_rn(v);
        __nv_bfloat16 lb = __float2bfloat16_rn(v - __bfloat162float(hb));
        size_t base = (size_t)(ch * NF + k) * 96;
        g_whl[base + n] = hb;
        g_whl[base + 48 + n] = lb;
    }
}

/* ---------------- fc1 + relu -> g_h (FFMA) ---------------- */
__global__ __launch_bounds__(256, 1) void k_fc1(const float* __restrict__ ea,
                                                const float* __restrict__ w1,
                                                const float* __restrict__ b1) {
    extern __shared__ float sm[];
    float* sE = sm;            /* [144][132] */
    float* sW = sm + 19008;    /* [144][144] */
    int tid = threadIdx.x, tx = tid & 7, ty = tid >> 3;
    int e0 = blockIdx.x * EPB;

    for (int x = tid; x < EPB * NF; x += 256) {
        int e = x / NF, k = x - e * NF;
        sE[k * 132 + e] = (e0 + e < NE) ? ea[(size_t)(e0 + e) * NF + k] : 0.f;
    }
    for (int x = tid; x < NF * NF; x += 256) sW[x] = w1[x];
    __syncthreads();

    float acc[4][18];
#pragma unroll
    for (int r = 0; r < 4; r++)
#pragma unroll
        for (int j = 0; j < 18; j++) acc[r][j] = 0.f;

    for (int k = 0; k < NF; k++) {
        float4 hv = *(const float4*)&sE[k * 132 + ty * 4];
        float wv[18];
#pragma unroll
        for (int j = 0; j < 18; j++) wv[j] = sW[k * NF + tx * 18 + j];
#pragma unroll
        for (int j = 0; j < 18; j++) {
            acc[0][j] = fmaf(hv.x, wv[j], acc[0][j]);
            acc[1][j] = fmaf(hv.y, wv[j], acc[1][j]);
            acc[2][j] = fmaf(hv.z, wv[j], acc[2][j]);
            acc[3][j] = fmaf(hv.w, wv[j], acc[3][j]);
        }
    }
#pragma unroll
    for (int r = 0; r < 4; r++) {
        int e = e0 + ty * 4 + r;
        if (e < NE) {
#pragma unroll
            for (int j = 0; j < 18; j++) {
                int o = tx * 18 + j;
                g_h[(size_t)e * NF + o] = fmaxf(acc[r][j] + b1[o], 0.f);
            }
        }
    }
}

/* -------- fused fc2 (mma.sync, A-in-regs, cp.async B pipeline) -------- */
__global__ __launch_bounds__(256, 1) void k_main(const float* __restrict__ na,
                                                 const float* __restrict__ esh,
                                                 const float* __restrict__ b2,
                                                 const int* __restrict__ ei) {
    extern __shared__ char smc[];
    uint32_t smb = smem_u32(smc);
    float* sCS = (float*)(smc + OFF_CS);
    float* sU  = (float*)(smc + OFF_U);
    float* sV  = (float*)(smc + OFF_V);
    float* s0  = (float*)(smc + OFF_S0);
    float* s1  = (float*)(smc + OFF_S1);
    int*   sS  = (int*)(smc + OFF_SS);
    float* aP  = (float*)(smc + OFF_AP);
    float* aQ  = (float*)(smc + OFF_AQ);

    int tid = threadIdx.x, lane = tid & 31, warp = tid >> 5;
    int gid = lane >> 2, tig = lane & 3;
    int eg = warp >> 1, cg = warp & 1;
    int e0 = blockIdx.x * EPB;

    /* smem prep */
    for (int x = tid; x < EPB * IND; x += 256) {
        int e = x / IND, d = x - e * IND;
        float v = 0.f;
        if (e0 + e < NE) { int dst = ei[NE + e0 + e]; v = na[dst * IND + d]; }
        if (d < NS) sU[e * NS + d] = A_SS * v;
        else        sV[e * 30 + d - NS] = A_VV * v;
    }
    if (tid < EPB) {
        int egl = e0 + tid;
        if (egl < NE) {
            sS[tid] = ei[egl]; s0[tid] = esh[egl * 4];
            s1[tid * 3] = esh[egl * 4 + 1]; s1[tid * 3 + 1] = esh[egl * 4 + 2];
            s1[tid * 3 + 2] = esh[egl * 4 + 3];
        } else {
            sS[tid] = 0; s0[tid] = 0.f;
            s1[tid * 3] = s1[tid * 3 + 1] = s1[tid * 3 + 2] = 0.f;
        }
    }
    for (int x = tid; x < EPB * 40; x += 256) aP[x] = 0.f;  /* aP,aQ contiguous */
    __syncthreads();
    for (int x = tid; x < EPB * 58; x += 256) {
        int e = x / 58, i = x - e * 58;
        if (i < 48) sCS[x] = s0[e] * sU[e * 48 + i];
        else {
            int ii = i - 48;
            sCS[x] = ISQ3 * (sV[e * 30 + ii * 3] * s1[e * 3] +
                             sV[e * 30 + ii * 3 + 1] * s1[e * 3 + 1] +
                             sV[e * 30 + ii * 3 + 2] * s1[e * 3 + 2]);
        }
    }

    /* A fragments in registers, chunk-invariant (hi/lo bf16 split) */
    uint32_t AH[2][9][4], AL[2][9][4];
#pragma unroll
    for (int mt = 0; mt < 2; mt++) {
        int r0 = eg * 32 + mt * 16 + gid;
#pragma unroll
        for (int kt = 0; kt < 9; kt++) {
#pragma unroll
            for (int q = 0; q < 4; q++) {
                int row = r0 + (q & 1) * 8;
                int k = kt * 16 + tig * 2 + (q >> 1) * 8;
                float f0 = 0.f, f1 = 0.f;
                if (e0 + row < NE) {
                    const float* p = &g_h[(size_t)(e0 + row) * NF + k];
                    f0 = p[0]; f1 = p[1];
                }
                __nv_bfloat16 h0 = __float2bfloat16_rn(f0), h1 = __float2bfloat16_rn(f1);
                AH[mt][kt][q] = (uint32_t)__bfloat16_as_ushort(h0) |
                                ((uint32_t)__bfloat16_as_ushort(h1) << 16);
                AL[mt][kt][q] = pkbf(f0 - __bfloat162float(h0), f1 - __bfloat162float(h1));
            }
        }
    }

    /* B ldmatrix addresses (warp col-group cg) */
    uint32_t a4 = smb + OFF_B + cg * 48 + (lane & 15) * 112 + (lane >> 4) * 16;
    uint32_t a2 = smb + OFF_B + cg * 48 + (lane & 15) * 112 + 32;

    float acc[2][3][4];
#pragma unroll
    for (int mt = 0; mt < 2; mt++)
#pragma unroll
        for (int nt = 0; nt < 3; nt++)
#pragma unroll
            for (int q = 0; q < 4; q++) acc[mt][nt][q] = 0.f;

    /* prologue fill chunk 0 */
    {
        const char* src = (const char*)g_whl;
        for (int x = tid; x < 1728; x += 256) {
            int k = x / 12, part = x - k * 12;
            uint32_t dst = smb + OFF_B + (part < 6 ? 0 : 16128) + k * 112 + (part % 6) * 16;
            cpa16(dst, src + k * 192 + part * 16);
        }
        CPA_COMMIT();
    }

    for (int cc = 0; cc < NCH; cc++) {
        int buf = cc & 1;
        CPA_WAIT0();
        __syncthreads();   /* B(cc) visible; buf^1 reads (chunk cc-1) done */
        if (cc + 1 < NCH) {
            const char* src = (const char*)g_whl + (size_t)(cc + 1) * 27648;
            uint32_t dstb = smb + OFF_B + (buf ^ 1) * 32256;
            for (int x = tid; x < 1728; x += 256) {
                int k = x / 12, part = x - k * 12;
                cpa16(dstb + (part < 6 ? 0 : 16128) + k * 112 + (part % 6) * 16,
                      (const char*)src + k * 192 + part * 16);
            }
            CPA_COMMIT();
        }

        float d[2][3][4];
#pragma unroll
        for (int mt = 0; mt < 2; mt++)
#pragma unroll
            for (int nt = 0; nt < 3; nt++)
#pragma unroll
                for (int q = 0; q < 4; q++) d[mt][nt][q] = 0.f;

        uint32_t bofs = buf * 32256;
#pragma unroll
        for (int kt = 0; kt < 9; kt++) {
            uint32_t bh[4], bl[4], bh2[2], bl2[2];
            ldsm4t(bh, a4 + bofs + kt * 1792);
            ldsm4t(bl, a4 + bofs + 16128 + kt * 1792);
            ldsm2t(bh2, a2 + bofs + kt * 1792);
            ldsm2t(bl2, a2 + bofs + 16128 + kt * 1792);
#pragma unroll
            for (int mt = 0; mt < 2; mt++) {
                mma16816(d[mt][0], AH[mt][kt], bh[0], bh[1]);
                mma16816(d[mt][0], AL[mt][kt], bh[0], bh[1]);
                mma16816(d[mt][0], AH[mt][kt], bl[0], bl[1]);
                mma16816(d[mt][1], AH[mt][kt], bh[2], bh[3]);
                mma16816(d[mt][1], AL[mt][kt], bh[2], bh[3]);
                mma16816(d[mt][1], AH[mt][kt], bl[2], bl[3]);
                mma16816(d[mt][2], AH[mt][kt], bh2[0], bh2[1]);
                mma16816(d[mt][2], AL[mt][kt], bh2[0], bh2[1]);
                mma16816(d[mt][2], AH[mt][kt], bl2[0], bl2[1]);
            }
        }

        /* consume */
        const float* bp = b2 + cc * 48;
        if (cc < 58) {
#pragma unroll
            for (int mt = 0; mt < 2; mt++) {
                int er0 = eg * 32 + mt * 16 + gid;
                float cf0 = sCS[er0 * 58 + cc], cf1 = sCS[(er0 + 8) * 58 + cc];
#pragma unroll
                for (int nt = 0; nt < 3; nt++) {
                    int col = cg * 24 + nt * 8 + tig * 2;
                    float b0v = bp[col], b1v = bp[col + 1];
                    acc[mt][nt][0] = fmaf(cf0, d[mt][nt][0] + b0v, acc[mt][nt][0]);
                    acc[mt][nt][1] = fmaf(cf0, d[mt][nt][1] + b1v, acc[mt][nt][1]);
                    acc[mt][nt][2] = fmaf(cf1, d[mt][nt][2] + b0v, acc[mt][nt][2]);
                    acc[mt][nt][3] = fmaf(cf1, d[mt][nt][3] + b1v, acc[mt][nt][3]);
                }
            }
        } else if (cc < 68) {
#pragma unroll
            for (int nt = 0; nt < 3; nt++) {
#pragma unroll
                for (int j = 0; j < 2; j++) {
                    int col = cg * 24 + nt * 8 + tig * 2 + j;
                    int tt = (cc - 58) * 48 + col;
                    int i = tt / 10, o = tt - i * 10;
                    float bb = bp[col];
#pragma unroll
                    for (int mt = 0; mt < 2; mt++) {
                        int er0 = eg * 32 + mt * 16 + gid;
                        atomicAdd(&aP[er0 * 10 + o],
                                  sU[er0 * 48 + i] * (d[mt][nt][j] + bb));
                        atomicAdd(&aP[(er0 + 8) * 10 + o],
                                  sU[(er0 + 8) * 48 + i] * (d[mt][nt][2 + j] + bb));
                    }
                }
            }
        } else {
#pragma unroll
            for (int nt = 0; nt < 3; nt++) {
#pragma unroll
                for (int j = 0; j < 2; j++) {
                    int col = cg * 24 + nt * 8 + tig * 2 + j;
                    int tt = (cc - 68) * 48 + col;
                    if (tt < 100) {
                        int i = tt / 10, o = tt - i * 10;
                        float bb = bp[col];
#pragma unroll
                        for (int mt = 0; mt < 2; mt++) {
                            int er0 = eg * 32 + mt * 16 + gid;
                            float w0 = d[mt][nt][j] + bb;
                            float w1v = d[mt][nt][2 + j] + bb;
                            const float* vp0 = &sV[er0 * 30 + i * 3];
                            const float* vp1 = &sV[(er0 + 8) * 30 + i * 3];
                            atomicAdd(&aQ[er0 * 30 + o * 3],     vp0[0] * w0);
                            atomicAdd(&aQ[er0 * 30 + o * 3 + 1], vp0[1] * w0);
                            atomicAdd(&aQ[er0 * 30 + o * 3 + 2], vp0[2] * w0);
                            atomicAdd(&aQ[(er0 + 8) * 30 + o * 3],     vp1[0] * w1v);
                            atomicAdd(&aQ[(er0 + 8) * 30 + o * 3 + 1], vp1[1] * w1v);
                            atomicAdd(&aQ[(er0 + 8) * 30 + o * 3 + 2], vp1[2] * w1v);
                        }
                    }
                }
            }
        }
    }
    __syncthreads();

    /* scatter out_s fragments */
#pragma unroll
    for (int mt = 0; mt < 2; mt++) {
        int er0 = eg * 32 + mt * 16 + gid;
        int eg0 = e0 + er0, eg1 = eg0 + 8;
        int base0 = sS[er0] * IND, base1 = sS[er0 + 8] * IND;
#pragma unroll
        for (int nt = 0; nt < 3; nt++) {
#pragma unroll
            for (int j = 0; j < 2; j++) {
                int col = cg * 24 + nt * 8 + tig * 2 + j;
                if (eg0 < NE) atomicAdd(&g_sum[base0 + col], acc[mt][nt][j]);
                if (eg1 < NE) atomicAdd(&g_sum[base1 + col], acc[mt][nt][2 + j]);
            }
        }
    }
    /* vector part */
    for (int x = tid; x < EPB * 30; x += 256) {
        int e = x / 30, t = x - e * 30, o = t / 3, ccp = t - o * 3;
        if (e0 + e < NE) {
            float v = s1[e * 3 + ccp] * aP[e * 10 + o] + s0[e] * aQ[e * 30 + t];
            atomicAdd(&g_sum[sS[e] * IND + NS + t], v);
        }
    }
    if (tid < EPB && e0 + tid < NE) atomicAdd(&g_cnt[sS[tid]], 1.f);
}

/* ---------------- epilogue ---------------- */
__global__ void k_zero() {
    int i = blockIdx.x * blockDim.x + threadIdx.x, st = gridDim.x * blockDim.x;
    for (int x = i; x < NN * IND; x += st) g_sum[x] = 0.f;
    for (int x = i; x < NN; x += st) g_cnt[x] = 0.f;
    if (i < 2 * NS + NV) g_stat[i] = 0.f;
}
__global__ void k_pre(const float* __restrict__ na) {
    int i = blockIdx.x * blockDim.x + threadIdx.x, st = gridDim.x * blockDim.x;
    for (int x = i; x < NN * IND; x += st) {
        int n = x / IND;
        g_pre[x] = g_sum[x] / fmaxf(g_cnt[n], 1.f) + na[x];
    }
}
__global__ __launch_bounds__(256) void k_stat() {
    __shared__ float r1[256], r2[256];
    int b = blockIdx.x, tid = threadIdx.x;
    float s = 0.f, q = 0.f;
    if (b < NS) {
        for (int n = tid; n < NN; n += 256) { float v = g_pre[n * IND + b]; s += v; q += v * v; }
    } else {
        int i = b - NS;
        for (int n = tid; n < NN; n += 256) {
            const float* p = &g_pre[n * IND + NS + i * 3];
            s += p[0] * p[0] + p[1] * p[1] + p[2] * p[2];
        }
    }
    r1[tid] = s; r2[tid] = q; __syncthreads();
    for (int o = 128; o > 0; o >>= 1) {
        if (tid < o) { r1[tid] += r1[tid + o]; r2[tid] += r2[tid + o]; }
        __syncthreads();
    }
    if (tid == 0) {
        if (b < NS) { g_stat[b] = r1[0]; g_stat[NS + b] = r2[0]; }
        else g_stat[NS + b] = r1[0];
    }
}
__global__ void k_nrm(const float* __restrict__ bnw, const float* __restrict__ bnb) {
    int t = threadIdx.x;
    if (t < NS) {
        float mu = g_stat[t] * (1.f / NN);
        float var = g_stat[NS + t] * (1.f / NN) - mu * mu;
        float sc = bnw[t] * rsqrtf(var + EPSF);
        g_nrm[t] = sc; g_nrm[NS + t] = bnb[t] - mu * sc;
    } else if (t < NS + NV) {
        int i = t - NS;
        float fn = g_stat[2 * NS + i] * (1.f / (3.f * NN));
        g_nrm[2 * NS + i] = bnw[NS + i] * rsqrtf(fn + EPSF);
    }
}
__global__ void k_apply(float* __restrict__ out) {
    int i = blockIdx.x * blockDim.x + threadIdx.x, st = gridDim.x * blockDim.x;
    for (int x = i; x < NN * IND; x += st) {
        int n = x / IND, d = x - n * IND;
        out[x] = (d < NS) ? g_pre[x] * g_nrm[d] + g_nrm[NS + d]
                          : g_pre[x] * g_nrm[2 * NS + (d - NS) / 3];
    }
}

extern "C" void kernel_launch(void* const* d_in, const int* in_sizes, int n_in,
                              void* d_out, int out_size) {
    (void)in_sizes; (void)n_in; (void)out_size;
    const float* nattr = (const float*)d_in[0];
    const float* ea    = (const float*)d_in[1];
    const float* esh   = (const float*)d_in[2];
    const float* w1    = (const float*)d_in[3];
    const float* b1    = (const float*)d_in[4];
    const float* w2    = (const float*)d_in[5];
    const float* b2    = (const float*)d_in[6];
    const float* bnw   = (const float*)d_in[7];
    const float* bnb   = (const float*)d_in[8];
    const int*   ei    = (const int*)d_in[9];
    float* out = (float*)d_out;

    size_t sm1 = (size_t)(19008 + 20736) * 4;
    cudaFuncSetAttribute(k_fc1,  cudaFuncAttributeMaxDynamicSharedMemorySize, (int)sm1);
    cudaFuncSetAttribute(k_main, cudaFuncAttributeMaxDynamicSharedMemorySize, SMEMTOT);

    k_zero<<<512, 256>>>();
    k_wprep<<<(NCH * NF * 48 + 255) / 256, 256>>>(w2);
    k_fc1<<<NBLK, 256, sm1>>>(ea, w1, b1);
    k_main<<<NBLK, 256, SMEMTOT>>>(nattr, esh, b2, ei);
    k_pre<<<512, 256>>>(nattr);
    k_stat<<<NS + NV, 256>>>();
    k_nrm<<<1, 64>>>(bnw, bnb);
    k_apply<<<512, 256>>>(out);
}

// round 8
// speedup vs baseline: 4.3483x; 1.1499x over previous
#include <cuda_runtime.h>
#include <cuda_fp16.h>
#include <stdint.h>
#include <math.h>

#define NS 48
#define NV 10
#define NE 100000
#define NN 10000
#define NF 144
#define IND 78
#define WNUM 3364
#define EPB 128
#define NBLK ((NE + EPB - 1) / EPB)
#define NCH 71
#define A_SS 0.102062072615966f
#define A_VV 0.223606797749979f
#define ISQ3 0.577350269189626f
#define EPSF 1e-5f

/* ---- SMEM byte offsets (k_main) ---- */
#define OFF_B   0           /* [2 buf][hi 16128 | lo 16128] = 64512 */
#define OFF_CS  64512       /* [128][58] f32 = 29696 */
#define OFF_U   94208       /* [128][48] f32 = 24576 */
#define OFF_V   118784      /* [128][30] f32 = 15360 */
#define OFF_S0  134144      /* [128] f32 */
#define OFF_S1  134656      /* [128][3] f32 */
#define OFF_SS  136192      /* [128] int */
#define OFF_AP  136704      /* [128][10] f32 */
#define OFF_AQ  141824      /* [128][30] f32 */
#define SMEMTOT 157184

__device__ float g_h[(size_t)NE * NF];
__device__ __half g_whl[(size_t)NCH * NF * 96];  /* per chunk: [144][48hi|48lo] fp16 */
__device__ float g_sum[NN * IND];
__device__ float g_cnt[NN];
__device__ float g_pre[NN * IND];
__device__ float g_stat[2 * NS + NV];
__device__ float g_nrm[2 * NS + NV];

__device__ __forceinline__ uint32_t smem_u32(const void* p) {
    uint32_t a;
    asm("{ .reg .u64 t; cvta.to.shared.u64 t, %1; cvt.u32.u64 %0, t; }" : "=r"(a) : "l"(p));
    return a;
}
__device__ __forceinline__ void ldsm4t(uint32_t* r, uint32_t a) {
    asm volatile("ldmatrix.sync.aligned.m8n8.x4.trans.shared.b16 {%0,%1,%2,%3}, [%4];"
                 : "=r"(r[0]), "=r"(r[1]), "=r"(r[2]), "=r"(r[3]) : "r"(a));
}
__device__ __forceinline__ void ldsm2t(uint32_t* r, uint32_t a) {
    asm volatile("ldmatrix.sync.aligned.m8n8.x2.trans.shared.b16 {%0,%1}, [%2];"
                 : "=r"(r[0]), "=r"(r[1]) : "r"(a));
}
__device__ __forceinline__ void mma16816(float* d, const uint32_t* a,
                                         uint32_t b0, uint32_t b1) {
    asm volatile("mma.sync.aligned.m16n8k16.row.col.f32.f16.f16.f32 "
                 "{%0,%1,%2,%3}, {%4,%5,%6,%7}, {%8,%9}, {%0,%1,%2,%3};"
                 : "+f"(d[0]), "+f"(d[1]), "+f"(d[2]), "+f"(d[3])
                 : "r"(a[0]), "r"(a[1]), "r"(a[2]), "r"(a[3]), "r"(b0), "r"(b1));
}
__device__ __forceinline__ void cpa16(uint32_t dst, const void* src) {
    asm volatile("cp.async.cg.shared.global [%0], [%1], 16;" :: "r"(dst), "l"(src));
}
#define CPA_COMMIT() asm volatile("cp.async.commit_group;" ::: "memory")
#define CPA_WAIT0()  asm volatile("cp.async.wait_group 0;" ::: "memory")
__device__ __forceinline__ uint32_t pkh(float x0, float x1) {
    __half h0 = __float2half_rn(x0), h1 = __float2half_rn(x1);
    return (uint32_t)__half_as_ushort(h0) | ((uint32_t)__half_as_ushort(h1) << 16);
}

/* -------- w2 -> fp16 hi/lo chunk blob -------- */
__global__ void k_wprep(const float* __restrict__ w2) {
    int x = blockIdx.x * blockDim.x + threadIdx.x;
    if (x < NCH * NF * 48) {
        int n = x % 48, t = x / 48, k = t % NF, ch = t / NF;
        int gc = ch * 48 + n;
        float v = (gc < WNUM) ? w2[(size_t)k * WNUM + gc] : 0.f;
        __half hb = __float2half_rn(v);
        __half lb = __float2half_rn(v - __half2float(hb));
        size_t base = (size_t)(ch * NF + k) * 96;
        g_whl[base + n] = hb;
        g_whl[base + 48 + n] = lb;
    }
}

/* ---------------- fc1 + relu -> g_h (FFMA fp32) ---------------- */
__global__ __launch_bounds__(256, 1) void k_fc1(const float* __restrict__ ea,
                                                const float* __restrict__ w1,
                                                const float* __restrict__ b1) {
    extern __shared__ float sm[];
    float* sE = sm;            /* [144][132] */
    float* sW = sm + 19008;    /* [144][144] */
    int tid = threadIdx.x, tx = tid & 7, ty = tid >> 3;
    int e0 = blockIdx.x * EPB;

    for (int x = tid; x < EPB * NF; x += 256) {
        int e = x / NF, k = x - e * NF;
        sE[k * 132 + e] = (e0 + e < NE) ? ea[(size_t)(e0 + e) * NF + k] : 0.f;
    }
    for (int x = tid; x < NF * NF; x += 256) sW[x] = w1[x];
    __syncthreads();

    float acc[4][18];
#pragma unroll
    for (int r = 0; r < 4; r++)
#pragma unroll
        for (int j = 0; j < 18; j++) acc[r][j] = 0.f;

    for (int k = 0; k < NF; k++) {
        float4 hv = *(const float4*)&sE[k * 132 + ty * 4];
        float wv[18];
#pragma unroll
        for (int j = 0; j < 18; j++) wv[j] = sW[k * NF + tx * 18 + j];
#pragma unroll
        for (int j = 0; j < 18; j++) {
            acc[0][j] = fmaf(hv.x, wv[j], acc[0][j]);
            acc[1][j] = fmaf(hv.y, wv[j], acc[1][j]);
            acc[2][j] = fmaf(hv.z, wv[j], acc[2][j]);
            acc[3][j] = fmaf(hv.w, wv[j], acc[3][j]);
        }
    }
#pragma unroll
    for (int r = 0; r < 4; r++) {
        int e = e0 + ty * 4 + r;
        if (e < NE) {
#pragma unroll
            for (int j = 0; j < 18; j++) {
                int o = tx * 18 + j;
                g_h[(size_t)e * NF + o] = fmaxf(acc[r][j] + b1[o], 0.f);
            }
        }
    }
}

/* -------- fused fc2 (fp16 mma 2-product, A-in-regs, cp.async B) -------- */
__global__ __launch_bounds__(256, 1) void k_main(const float* __restrict__ na,
                                                 const float* __restrict__ esh,
                                                 const float* __restrict__ b2,
                                                 const int* __restrict__ ei) {
    extern __shared__ char smc[];
    uint32_t smb = smem_u32(smc);
    float* sCS = (float*)(smc + OFF_CS);
    float* sU  = (float*)(smc + OFF_U);
    float* sV  = (float*)(smc + OFF_V);
    float* s0  = (float*)(smc + OFF_S0);
    float* s1  = (float*)(smc + OFF_S1);
    int*   sS  = (int*)(smc + OFF_SS);
    float* aP  = (float*)(smc + OFF_AP);
    float* aQ  = (float*)(smc + OFF_AQ);

    int tid = threadIdx.x, lane = tid & 31, warp = tid >> 5;
    int gid = lane >> 2, tig = lane & 3;
    int eg = warp >> 1, cg = warp & 1;
    int e0 = blockIdx.x * EPB;

    /* smem prep */
    for (int x = tid; x < EPB * IND; x += 256) {
        int e = x / IND, d = x - e * IND;
        float v = 0.f;
        if (e0 + e < NE) { int dst = ei[NE + e0 + e]; v = na[dst * IND + d]; }
        if (d < NS) sU[e * NS + d] = A_SS * v;
        else        sV[e * 30 + d - NS] = A_VV * v;
    }
    if (tid < EPB) {
        int egl = e0 + tid;
        if (egl < NE) {
            sS[tid] = ei[egl]; s0[tid] = esh[egl * 4];
            s1[tid * 3] = esh[egl * 4 + 1]; s1[tid * 3 + 1] = esh[egl * 4 + 2];
            s1[tid * 3 + 2] = esh[egl * 4 + 3];
        } else {
            sS[tid] = 0; s0[tid] = 0.f;
            s1[tid * 3] = s1[tid * 3 + 1] = s1[tid * 3 + 2] = 0.f;
        }
    }
    for (int x = tid; x < EPB * 40; x += 256) aP[x] = 0.f;  /* aP,aQ contiguous */
    __syncthreads();
    for (int x = tid; x < EPB * 58; x += 256) {
        int e = x / 58, i = x - e * 58;
        if (i < 48) sCS[x] = s0[e] * sU[e * 48 + i];
        else {
            int ii = i - 48;
            sCS[x] = ISQ3 * (sV[e * 30 + ii * 3] * s1[e * 3] +
                             sV[e * 30 + ii * 3 + 1] * s1[e * 3 + 1] +
                             sV[e * 30 + ii * 3 + 2] * s1[e * 3 + 2]);
        }
    }

    /* A fragments in registers, chunk-invariant, fp16 single */
    uint32_t AH[2][9][4];
#pragma unroll
    for (int mt = 0; mt < 2; mt++) {
        int r0 = eg * 32 + mt * 16 + gid;
#pragma unroll
        for (int kt = 0; kt < 9; kt++) {
#pragma unroll
            for (int q = 0; q < 4; q++) {
                int row = r0 + (q & 1) * 8;
                int k = kt * 16 + tig * 2 + (q >> 1) * 8;
                float f0 = 0.f, f1 = 0.f;
                if (e0 + row < NE) {
                    const float* p = &g_h[(size_t)(e0 + row) * NF + k];
                    f0 = p[0]; f1 = p[1];
                }
                AH[mt][kt][q] = pkh(f0, f1);
            }
        }
    }

    /* B ldmatrix addresses (warp col-group cg) */
    uint32_t a4 = smb + OFF_B + cg * 48 + (lane & 15) * 112 + (lane >> 4) * 16;
    uint32_t a2 = smb + OFF_B + cg * 48 + (lane & 15) * 112 + 32;

    float acc[2][3][4];
#pragma unroll
    for (int mt = 0; mt < 2; mt++)
#pragma unroll
        for (int nt = 0; nt < 3; nt++)
#pragma unroll
            for (int q = 0; q < 4; q++) acc[mt][nt][q] = 0.f;

    /* prologue fill chunk 0 */
    {
        const char* src = (const char*)g_whl;
        for (int x = tid; x < 1728; x += 256) {
            int k = x / 12, part = x - k * 12;
            uint32_t dst = smb + OFF_B + (part < 6 ? 0 : 16128) + k * 112 + (part % 6) * 16;
            cpa16(dst, src + k * 192 + part * 16);
        }
        CPA_COMMIT();
    }

    for (int cc = 0; cc < NCH; cc++) {
        int buf = cc & 1;
        CPA_WAIT0();
        __syncthreads();   /* B(cc) visible; other buf's reads done */
        if (cc + 1 < NCH) {
            const char* src = (const char*)g_whl + (size_t)(cc + 1) * 27648;
            uint32_t dstb = smb + OFF_B + (buf ^ 1) * 32256;
            for (int x = tid; x < 1728; x += 256) {
                int k = x / 12, part = x - k * 12;
                cpa16(dstb + (part < 6 ? 0 : 16128) + k * 112 + (part % 6) * 16,
                      (const char*)src + k * 192 + part * 16);
            }
            CPA_COMMIT();
        }

        float d[2][3][4];
#pragma unroll
        for (int mt = 0; mt < 2; mt++)
#pragma unroll
            for (int nt = 0; nt < 3; nt++)
#pragma unroll
                for (int q = 0; q < 4; q++) d[mt][nt][q] = 0.f;

        uint32_t bofs = buf * 32256;
        uint32_t bh[6], bl[6];
        ldsm4t(bh, a4 + bofs);
        ldsm4t(bl, a4 + bofs + 16128);
        ldsm2t(bh + 4, a2 + bofs);
        ldsm2t(bl + 4, a2 + bofs + 16128);
#pragma unroll
        for (int kt = 0; kt < 9; kt++) {
            uint32_t nh[6], nl[6];
            if (kt < 8) {
                ldsm4t(nh, a4 + bofs + (kt + 1) * 1792);
                ldsm4t(nl, a4 + bofs + 16128 + (kt + 1) * 1792);
                ldsm2t(nh + 4, a2 + bofs + (kt + 1) * 1792);
                ldsm2t(nl + 4, a2 + bofs + 16128 + (kt + 1) * 1792);
            }
#pragma unroll
            for (int mt = 0; mt < 2; mt++) {
                mma16816(d[mt][0], AH[mt][kt], bh[0], bh[1]);
                mma16816(d[mt][0], AH[mt][kt], bl[0], bl[1]);
                mma16816(d[mt][1], AH[mt][kt], bh[2], bh[3]);
                mma16816(d[mt][1], AH[mt][kt], bl[2], bl[3]);
                mma16816(d[mt][2], AH[mt][kt], bh[4], bh[5]);
                mma16816(d[mt][2], AH[mt][kt], bl[4], bl[5]);
            }
            if (kt < 8) {
#pragma unroll
                for (int q = 0; q < 6; q++) { bh[q] = nh[q]; bl[q] = nl[q]; }
            }
        }

        /* consume */
        const float* bp = b2 + cc * 48;
        if (cc < 58) {
#pragma unroll
            for (int mt = 0; mt < 2; mt++) {
                int er0 = eg * 32 + mt * 16 + gid;
                float cf0 = sCS[er0 * 58 + cc], cf1 = sCS[(er0 + 8) * 58 + cc];
#pragma unroll
                for (int nt = 0; nt < 3; nt++) {
                    int col = cg * 24 + nt * 8 + tig * 2;
                    float b0v = bp[col], b1v = bp[col + 1];
                    acc[mt][nt][0] = fmaf(cf0, d[mt][nt][0] + b0v, acc[mt][nt][0]);
                    acc[mt][nt][1] = fmaf(cf0, d[mt][nt][1] + b1v, acc[mt][nt][1]);
                    acc[mt][nt][2] = fmaf(cf1, d[mt][nt][2] + b0v, acc[mt][nt][2]);
                    acc[mt][nt][3] = fmaf(cf1, d[mt][nt][3] + b1v, acc[mt][nt][3]);
                }
            }
        } else if (cc < 68) {
#pragma unroll
            for (int nt = 0; nt < 3; nt++) {
#pragma unroll
                for (int j = 0; j < 2; j++) {
                    int col = cg * 24 + nt * 8 + tig * 2 + j;
                    int tt = (cc - 58) * 48 + col;
                    int i = tt / 10, o = tt - i * 10;
                    float bb = bp[col];
#pragma unroll
                    for (int mt = 0; mt < 2; mt++) {
                        int er0 = eg * 32 + mt * 16 + gid;
                        atomicAdd(&aP[er0 * 10 + o],
                                  sU[er0 * 48 + i] * (d[mt][nt][j] + bb));
                        atomicAdd(&aP[(er0 + 8) * 10 + o],
                                  sU[(er0 + 8) * 48 + i] * (d[mt][nt][2 + j] + bb));
                    }
                }
            }
        } else {
#pragma unroll
            for (int nt = 0; nt < 3; nt++) {
#pragma unroll
                for (int j = 0; j < 2; j++) {
                    int col = cg * 24 + nt * 8 + tig * 2 + j;
                    int tt = (cc - 68) * 48 + col;
                    if (tt < 100) {
                        int i = tt / 10, o = tt - i * 10;
                        float bb = bp[col];
#pragma unroll
                        for (int mt = 0; mt < 2; mt++) {
                            int er0 = eg * 32 + mt * 16 + gid;
                            float w0 = d[mt][nt][j] + bb;
                            float w1v = d[mt][nt][2 + j] + bb;
                            const float* vp0 = &sV[er0 * 30 + i * 3];
                            const float* vp1 = &sV[(er0 + 8) * 30 + i * 3];
                            atomicAdd(&aQ[er0 * 30 + o * 3],     vp0[0] * w0);
                            atomicAdd(&aQ[er0 * 30 + o * 3 + 1], vp0[1] * w0);
                            atomicAdd(&aQ[er0 * 30 + o * 3 + 2], vp0[2] * w0);
                            atomicAdd(&aQ[(er0 + 8) * 30 + o * 3],     vp1[0] * w1v);
                            atomicAdd(&aQ[(er0 + 8) * 30 + o * 3 + 1], vp1[1] * w1v);
                            atomicAdd(&aQ[(er0 + 8) * 30 + o * 3 + 2], vp1[2] * w1v);
                        }
                    }
                }
            }
        }
    }
    __syncthreads();

    /* scatter out_s fragments */
#pragma unroll
    for (int mt = 0; mt < 2; mt++) {
        int er0 = eg * 32 + mt * 16 + gid;
        int eg0 = e0 + er0, eg1 = eg0 + 8;
        int base0 = sS[er0] * IND, base1 = sS[er0 + 8] * IND;
#pragma unroll
        for (int nt = 0; nt < 3; nt++) {
#pragma unroll
            for (int j = 0; j < 2; j++) {
                int col = cg * 24 + nt * 8 + tig * 2 + j;
                if (eg0 < NE) atomicAdd(&g_sum[base0 + col], acc[mt][nt][j]);
                if (eg1 < NE) atomicAdd(&g_sum[base1 + col], acc[mt][nt][2 + j]);
            }
        }
    }
    /* vector part */
    for (int x = tid; x < EPB * 30; x += 256) {
        int e = x / 30, t = x - e * 30, o = t / 3, ccp = t - o * 3;
        if (e0 + e < NE) {
            float v = s1[e * 3 + ccp] * aP[e * 10 + o] + s0[e] * aQ[e * 30 + t];
            atomicAdd(&g_sum[sS[e] * IND + NS + t], v);
        }
    }
    if (tid < EPB && e0 + tid < NE) atomicAdd(&g_cnt[sS[tid]], 1.f);
}

/* ---------------- epilogue ---------------- */
__global__ void k_zero() {
    int i = blockIdx.x * blockDim.x + threadIdx.x, st = gridDim.x * blockDim.x;
    for (int x = i; x < NN * IND; x += st) g_sum[x] = 0.f;
    for (int x = i; x < NN; x += st) g_cnt[x] = 0.f;
    if (i < 2 * NS + NV) g_stat[i] = 0.f;
}
__global__ void k_pre(const float* __restrict__ na) {
    int i = blockIdx.x * blockDim.x + threadIdx.x, st = gridDim.x * blockDim.x;
    for (int x = i; x < NN * IND; x += st) {
        int n = x / IND;
        g_pre[x] = g_sum[x] / fmaxf(g_cnt[n], 1.f) + na[x];
    }
}
__global__ __launch_bounds__(256) void k_stat() {
    __shared__ float r1[256], r2[256];
    int b = blockIdx.x, tid = threadIdx.x;
    float s = 0.f, q = 0.f;
    if (b < NS) {
        for (int n = tid; n < NN; n += 256) { float v = g_pre[n * IND + b]; s += v; q += v * v; }
    } else {
        int i = b - NS;
        for (int n = tid; n < NN; n += 256) {
            const float* p = &g_pre[n * IND + NS + i * 3];
            s += p[0] * p[0] + p[1] * p[1] + p[2] * p[2];
        }
    }
    r1[tid] = s; r2[tid] = q; __syncthreads();
    for (int o = 128; o > 0; o >>= 1) {
        if (tid < o) { r1[tid] += r1[tid + o]; r2[tid] += r2[tid + o]; }
        __syncthreads();
    }
    if (tid == 0) {
        if (b < NS) { g_stat[b] = r1[0]; g_stat[NS + b] = r2[0]; }
        else g_stat[NS + b] = r1[0];
    }
}
__global__ void k_nrm(const float* __restrict__ bnw, const float* __restrict__ bnb) {
    int t = threadIdx.x;
    if (t < NS) {
        float mu = g_stat[t] * (1.f / NN);
        float var = g_stat[NS + t] * (1.f / NN) - mu * mu;
        float sc = bnw[t] * rsqrtf(var + EPSF);
        g_nrm[t] = sc; g_nrm[NS + t] = bnb[t] - mu * sc;
    } else if (t < NS + NV) {
        int i = t - NS;
        float fn = g_stat[2 * NS + i] * (1.f / (3.f * NN));
        g_nrm[2 * NS + i] = bnw[NS + i] * rsqrtf(fn + EPSF);
    }
}
__global__ void k_apply(float* __restrict__ out) {
    int i = blockIdx.x * blockDim.x + threadIdx.x, st = gridDim.x * blockDim.x;
    for (int x = i; x < NN * IND; x += st) {
        int n = x / IND, d = x - n * IND;
        out[x] = (d < NS) ? g_pre[x] * g_nrm[d] + g_nrm[NS + d]
                          : g_pre[x] * g_nrm[2 * NS + (d - NS) / 3];
    }
}

extern "C" void kernel_launch(void* const* d_in, const int* in_sizes, int n_in,
                              void* d_out, int out_size) {
    (void)in_sizes; (void)n_in; (void)out_size;
    const float* nattr = (const float*)d_in[0];
    const float* ea    = (const float*)d_in[1];
    const float* esh   = (const float*)d_in[2];
    const float* w1    = (const float*)d_in[3];
    const float* b1    = (const float*)d_in[4];
    const float* w2    = (const float*)d_in[5];
    const float* b2    = (const float*)d_in[6];
    const float* bnw   = (const float*)d_in[7];
    const float* bnb   = (const float*)d_in[8];
    const int*   ei    = (const int*)d_in[9];
    float* out = (float*)d_out;

    size_t sm1 = (size_t)(19008 + 20736) * 4;
    cudaFuncSetAttribute(k_fc1,  cudaFuncAttributeMaxDynamicSharedMemorySize, (int)sm1);
    cudaFuncSetAttribute(k_main, cudaFuncAttributeMaxDynamicSharedMemorySize, SMEMTOT);

    k_zero<<<512, 256>>>();
    k_wprep<<<(NCH * NF * 48 + 255) / 256, 256>>>(w2);
    k_fc1<<<NBLK, 256, sm1>>>(ea, w1, b1);
    k_main<<<NBLK, 256, SMEMTOT>>>(nattr, esh, b2, ei);
    k_pre<<<512, 256>>>(nattr);
    k_stat<<<NS + NV, 256>>>();
    k_nrm<<<1, 64>>>(bnw, bnb);
    k_apply<<<512, 256>>>(out);
}